// round 3
// baseline (speedup 1.0000x reference)
#include <cuda_runtime.h>
#include <cstdint>
#include <math.h>

// Problem constants
#define B   64
#define M   1024
#define W   64
#define R   4
#define D   512
#define IF  471   // r*w + 3*w + 5*r + 3

// ---------------- scratch (device globals; no allocation allowed) ----------------
__device__ float g_iface[B * IF];
__device__ __align__(16) float g_keys[B * R * W];
__device__ float g_kstr[B * R];
__device__ float g_knorm[B * R];
__device__ __align__(16) float g_wkey[B * W];
__device__ float g_wknorm[B];
__device__ float g_ws[B];
__device__ __align__(16) float g_erase[B * W];
__device__ __align__(16) float g_wvec[B * W];
__device__ float g_ag[B], g_wg[B];
__device__ float g_rm[B * R * 3];
__device__ float g_usage[B * M];
__device__ float g_wc[B * M];
__device__ float g_allocw[B * M];
__device__ float g_ww[B * M];
__device__ float g_cw[B * R * M];
__device__ float g_fw[B * R * M];
__device__ __align__(16) float g_bwp[B * 8 * R * M];   // per-mtile bw partials (8 MB)
__device__ __align__(16) float g_newmem[B * M * W];

// ---------------- helpers ----------------
__device__ __forceinline__ float sigmoidf_(float x) { return 1.0f / (1.0f + expf(-x)); }
__device__ __forceinline__ float softplusf_(float x) { return (x > 20.0f) ? x : log1pf(expf(x)); }

__device__ __forceinline__ float warpMax_(float v) {
#pragma unroll
    for (int o = 16; o; o >>= 1) v = fmaxf(v, __shfl_xor_sync(0xffffffffu, v, o));
    return v;
}
__device__ __forceinline__ float warpSum_(float v) {
#pragma unroll
    for (int o = 16; o; o >>= 1) v += __shfl_xor_sync(0xffffffffu, v, o);
    return v;
}
__device__ __forceinline__ float blockMax_(float v, float* sh) {
    v = warpMax_(v);
    if ((threadIdx.x & 31) == 0) sh[threadIdx.x >> 5] = v;
    __syncthreads();
    float r = sh[threadIdx.x & 31];
    r = warpMax_(r);
    __syncthreads();
    return r;
}
__device__ __forceinline__ float blockSum_(float v, float* sh) {
    v = warpSum_(v);
    if ((threadIdx.x & 31) == 0) sh[threadIdx.x >> 5] = v;
    __syncthreads();
    float r = sh[threadIdx.x & 31];
    r = warpSum_(r);
    __syncthreads();
    return r;
}

// ---------------- K1: iface = xi @ W + bW ----------------
__global__ __launch_bounds__(512) void k_iface(const float* __restrict__ xi,
                                               const float* __restrict__ Wm,
                                               const float* __restrict__ bW) {
    int b = blockIdx.x, j = threadIdx.x;
    __shared__ float xs[D];
    xs[j] = xi[b * D + j];
    __syncthreads();
    if (j < IF) {
        float acc = bW[j];
#pragma unroll 8
        for (int i = 0; i < D; i++) acc = fmaf(xs[i], Wm[i * IF + j], acc);
        g_iface[b * IF + j] = acc;
    }
}

// ---------------- K2: parse iface + usage ----------------
__global__ __launch_bounds__(512) void k_prep(const float* __restrict__ read_weights,
                                              const float* __restrict__ write_weights,
                                              const float* __restrict__ usage_vector) {
    int b = blockIdx.x, t = threadIdx.x;
    const float* f = g_iface + b * IF;

    if (t < 256) g_keys[b * 256 + t] = f[t];
    if (t >= 256 && t < 320) { int i = t - 256; g_wkey[b * W + i] = f[260 + i]; }
    if (t >= 320 && t < 384) { int i = t - 320; g_erase[b * W + i] = sigmoidf_(f[325 + i]); }
    if (t >= 384 && t < 448) { int i = t - 384; g_wvec[b * W + i] = f[389 + i]; }
    if (t < 4) {
        float x = f[256 + t];
        g_kstr[b * 4 + t] = softplusf_(1.0f + fmaxf(x, 0.0f));
        float s = 0.0f;
        for (int i = 0; i < W; i++) { float v = f[t * W + i]; s = fmaf(v, v, s); }
        g_knorm[b * 4 + t] = sqrtf(s);
    }
    if (t == 4) {
        float x = f[324];
        g_ws[b] = softplusf_(1.0f + fmaxf(x, 0.0f));
        float s = 0.0f;
        for (int i = 0; i < W; i++) { float v = f[260 + i]; s = fmaf(v, v, s); }
        g_wknorm[b] = sqrtf(s);
    }
    if (t == 5) g_ag[b] = sigmoidf_(f[457]);
    if (t == 6) g_wg[b] = sigmoidf_(f[458]);
    if (t >= 8 && t < 11) {  // read_modes: softmax over r axis, per mode j
        int j = t - 8;
        float v[4], mx = -1e30f;
        for (int rr = 0; rr < 4; rr++) { v[rr] = f[458 + rr * 3 + j]; mx = fmaxf(mx, v[rr]); }
        float s = 0.0f;
        for (int rr = 0; rr < 4; rr++) { v[rr] = expf(v[rr] - mx); s += v[rr]; }
        for (int rr = 0; rr < 4; rr++) g_rm[b * 12 + rr * 3 + j] = v[rr] / s;
    }

    float fg[4];
#pragma unroll
    for (int rr = 0; rr < 4; rr++) fg[rr] = sigmoidf_(f[453 + rr]);
    for (int m = t; m < M; m += 512) {
        float uv = usage_vector[b * M + m];
        float wwo = write_weights[b * M + m];
        float u = uv + (1.0f - uv) * wwo;
        float psi = 1.0f;
#pragma unroll
        for (int rr = 0; rr < 4; rr++)
            psi *= (1.0f - fg[rr] * read_weights[(b * 4 + rr) * M + m]);
        g_usage[b * M + m] = u * psi;
    }
}

// ---------------- K3: write content weighting (softmax over m) ----------------
__global__ __launch_bounds__(1024) void k_write_content(const float* __restrict__ memory) {
    int b = blockIdx.x, t = threadIdx.x;
    __shared__ float4 key_s[16];
    __shared__ float dvals[M];
    __shared__ float red[32];
    if (t < 16) key_s[t] = ((const float4*)(g_wkey + b * W))[t];
    __syncthreads();
    float knorm = g_wknorm[b] + 1e-6f;
    float s = g_ws[b];
    int row = t >> 4, lane = t & 15;
    const float4* mem4 = (const float4*)(memory + (size_t)b * M * W);
    for (int g = 0; g < 16; g++) {
        int m = g * 64 + row;
        float4 v = mem4[m * 16 + lane];
        float4 k = key_s[lane];
        float dot = v.x * k.x + v.y * k.y + v.z * k.z + v.w * k.w;
        float ns  = v.x * v.x + v.y * v.y + v.z * v.z + v.w * v.w;
#pragma unroll
        for (int o = 8; o; o >>= 1) {
            dot += __shfl_xor_sync(0xffffffffu, dot, o);
            ns  += __shfl_xor_sync(0xffffffffu, ns, o);
        }
        if (lane == 0) dvals[m] = dot * s / ((sqrtf(ns) + 1e-6f) * knorm);
    }
    __syncthreads();
    float x = dvals[t];
    float mx = blockMax_(x, red);
    float e = expf(x - mx);
    float sm = blockSum_(e, red);
    g_wc[b * M + t] = e / sm;
}

// ---------------- K4: allocation (hybrid bitonic sort + warp-scan cumprod) ----------------
__global__ __launch_bounds__(1024) void k_allocation() {
    int b = blockIdx.x, t = threadIdx.x;
    int lane = t & 31, warp = t >> 5;
    __shared__ unsigned long long ks[M];
    __shared__ float wtot[32];

    float u = 1e-6f + (1.0f - 1e-6f) * g_usage[b * M + t];
    unsigned long long v = ((unsigned long long)__float_as_uint(u) << 32) | (unsigned)t;

    // rounds k=2..32 fully in registers (no barriers)
#pragma unroll
    for (int k = 2; k <= 32; k <<= 1) {
#pragma unroll
        for (int j = k >> 1; j > 0; j >>= 1) {
            unsigned long long c = __shfl_xor_sync(0xffffffffu, v, j);
            bool keepMin = ((t & j) == 0) == ((t & k) == 0);
            bool less = v < c;
            v = (less == keepMin) ? v : c;
        }
    }
    ks[t] = v;
    __syncthreads();

    // rounds k=64..1024: shared stages for j>=32, register stages for j<32
#pragma unroll
    for (int k = 64; k <= M; k <<= 1) {
        for (int j = k >> 1; j >= 32; j >>= 1) {
            unsigned long long a = ks[t];
            unsigned long long c = ks[t ^ j];
            bool keepMin = ((t & j) == 0) == ((t & k) == 0);
            bool less = a < c;
            v = (less == keepMin) ? a : c;
            __syncthreads();
            ks[t] = v;
            __syncthreads();
        }
#pragma unroll
        for (int j = 16; j > 0; j >>= 1) {
            unsigned long long c = __shfl_xor_sync(0xffffffffu, v, j);
            bool keepMin = ((t & j) == 0) == ((t & k) == 0);
            bool less = v < c;
            v = (less == keepMin) ? v : c;
        }
        if (k < M) { ks[t] = v; __syncthreads(); }
    }

    // inclusive product scan over sorted u
    float su = __uint_as_float((unsigned)(v >> 32));
    float p = su;
#pragma unroll
    for (int o = 1; o < 32; o <<= 1) {
        float q = __shfl_up_sync(0xffffffffu, p, o);
        if (lane >= o) p *= q;
    }
    if (lane == 31) wtot[warp] = p;
    __syncthreads();
    if (warp == 0) {
        float q = wtot[lane];
#pragma unroll
        for (int o = 1; o < 32; o <<= 1) {
            float rr = __shfl_up_sync(0xffffffffu, q, o);
            if (lane >= o) q *= rr;
        }
        wtot[lane] = q;
    }
    __syncthreads();
    if (warp > 0) p *= wtot[warp - 1];

    int idx = (int)(v & 0xffffffffULL);
    g_allocw[b * M + idx] = (1.0f - su) * p;
}

// ---------------- K5: fused ww + memory update + read content softmax ----------------
__global__ __launch_bounds__(1024) void k_memupdate_content(const float* __restrict__ memory) {
    int b = blockIdx.x, t = threadIdx.x;
    __shared__ float ww_s[M];
    __shared__ float4 rk_s[4 * 16];
    __shared__ float4 e_s[16], wv_s[16];
    __shared__ float d_s[4][M];
    __shared__ float red[32];

    float ag = g_ag[b], wg = g_wg[b];
    {
        float a = g_allocw[b * M + t];
        float wcv = g_wc[b * M + t];
        float ww = wg * (ag * a + (1.0f - ag) * wcv);
        ww_s[t] = ww;
        g_ww[b * M + t] = ww;
    }
    if (t < 64) rk_s[t] = ((const float4*)(g_keys + b * 256))[t];
    if (t >= 64 && t < 80) e_s[t - 64] = ((const float4*)(g_erase + b * W))[t - 64];
    if (t >= 80 && t < 96) wv_s[t - 80] = ((const float4*)(g_wvec + b * W))[t - 80];
    float kn[4], kstr[4];
#pragma unroll
    for (int rr = 0; rr < 4; rr++) { kn[rr] = g_knorm[b * 4 + rr] + 1e-6f; kstr[rr] = g_kstr[b * 4 + rr]; }
    __syncthreads();

    int row = t >> 4, lane = t & 15;
    const float4* mem4 = (const float4*)(memory + (size_t)b * M * W);
    float4* nm4 = (float4*)(g_newmem + (size_t)b * M * W);
    for (int g = 0; g < 16; g++) {
        int m = g * 64 + row;
        float wwm = ww_s[m];
        float4 v = mem4[m * 16 + lane];
        float4 e = e_s[lane], wv = wv_s[lane];
        float4 nm;
        nm.x = fmaf(v.x, fmaf(-wwm, e.x, 1.0f), wwm * wv.x);
        nm.y = fmaf(v.y, fmaf(-wwm, e.y, 1.0f), wwm * wv.y);
        nm.z = fmaf(v.z, fmaf(-wwm, e.z, 1.0f), wwm * wv.z);
        nm.w = fmaf(v.w, fmaf(-wwm, e.w, 1.0f), wwm * wv.w);
        nm4[m * 16 + lane] = nm;
        float ns = nm.x * nm.x + nm.y * nm.y + nm.z * nm.z + nm.w * nm.w;
        float dr[4];
#pragma unroll
        for (int rr = 0; rr < 4; rr++) {
            float4 k = rk_s[rr * 16 + lane];
            dr[rr] = nm.x * k.x + nm.y * k.y + nm.z * k.z + nm.w * k.w;
        }
#pragma unroll
        for (int o = 8; o; o >>= 1) {
            ns += __shfl_xor_sync(0xffffffffu, ns, o);
#pragma unroll
            for (int rr = 0; rr < 4; rr++) dr[rr] += __shfl_xor_sync(0xffffffffu, dr[rr], o);
        }
        if (lane == 0) {
            float inv = 1.0f / (sqrtf(ns) + 1e-6f);
#pragma unroll
            for (int rr = 0; rr < 4; rr++) d_s[rr][m] = dr[rr] * kstr[rr] * inv / kn[rr];
        }
    }
    __syncthreads();
#pragma unroll
    for (int rr = 0; rr < 4; rr++) {
        float x = d_s[rr][t];
        float mx = blockMax_(x, red);
        float e = expf(x - mx);
        float sm = blockSum_(e, red);
        g_cw[(b * 4 + rr) * M + t] = e / sm;
    }
}

// ---------------- K6: fused link-matrix kernel (fw/bw, NO atomics) ----------------
// new_link[m,n] = (m!=n) * ((1 - ww[m] - ww[n]) * L[m,n] + ww[m]*prec_old[n])
// fw[r][m] = sum_n NL[m,n]*rw_old[r][n]; bw[r][n] = sum_m NL[m,n]*rw_old[r][m]
__global__ __launch_bounds__(256) void k_link(const float* __restrict__ link,
                                              const float* __restrict__ precedence,
                                              const float* __restrict__ read_weights) {
    int mt = blockIdx.x;   // 8 tiles of 128 rows
    int b  = blockIdx.y;
    int t  = threadIdx.x;
    int warp = t >> 5, lane = t & 31;
    __shared__ __align__(16) float ww_s[M];
    __shared__ __align__(16) float pr_s[M];
    __shared__ __align__(16) float rw_s[4][M];
    __shared__ float fw_s[8][4][128];   // per-warp private partials (16 KB)

    for (int i = t; i < M; i += 256) {
        ww_s[i] = g_ww[b * M + i];
        pr_s[i] = precedence[b * M + i];
    }
    for (int i = t; i < 4 * M; i += 256) ((float*)rw_s)[i] = read_weights[b * 4 * M + i];
    __syncthreads();

    int n0 = t * 4;
    float4 pn  = *(const float4*)&pr_s[n0];
    float4 wwn = *(const float4*)&ww_s[n0];
    float4 rwn[4];
#pragma unroll
    for (int rr = 0; rr < 4; rr++) rwn[rr] = *(const float4*)&rw_s[rr][n0];
    float4 bwa[4];
#pragma unroll
    for (int rr = 0; rr < 4; rr++) bwa[rr] = make_float4(0.f, 0.f, 0.f, 0.f);

    const float4* L4 = (const float4*)(link + (size_t)b * M * M);

#pragma unroll 4
    for (int mi = 0; mi < 128; mi++) {
        int m = mt * 128 + mi;
        float wwm = ww_s[m];
        float cm = 1.0f - wwm;
        float r0 = rw_s[0][m], r1 = rw_s[1][m], r2 = rw_s[2][m], r3 = rw_s[3][m];
        float4 L = L4[(size_t)m * 256 + t];
        float nl0 = fmaf(L.x, cm - wwn.x, wwm * pn.x);
        float nl1 = fmaf(L.y, cm - wwn.y, wwm * pn.y);
        float nl2 = fmaf(L.z, cm - wwn.z, wwm * pn.z);
        float nl3 = fmaf(L.w, cm - wwn.w, wwm * pn.w);
        if (n0 + 0 == m) nl0 = 0.0f;
        if (n0 + 1 == m) nl1 = 0.0f;
        if (n0 + 2 == m) nl2 = 0.0f;
        if (n0 + 3 == m) nl3 = 0.0f;

        float f0 = nl0 * rwn[0].x + nl1 * rwn[0].y + nl2 * rwn[0].z + nl3 * rwn[0].w;
        float f1 = nl0 * rwn[1].x + nl1 * rwn[1].y + nl2 * rwn[1].z + nl3 * rwn[1].w;
        float f2 = nl0 * rwn[2].x + nl1 * rwn[2].y + nl2 * rwn[2].z + nl3 * rwn[2].w;
        float f3 = nl0 * rwn[3].x + nl1 * rwn[3].y + nl2 * rwn[3].z + nl3 * rwn[3].w;

        bwa[0].x = fmaf(nl0, r0, bwa[0].x); bwa[0].y = fmaf(nl1, r0, bwa[0].y);
        bwa[0].z = fmaf(nl2, r0, bwa[0].z); bwa[0].w = fmaf(nl3, r0, bwa[0].w);
        bwa[1].x = fmaf(nl0, r1, bwa[1].x); bwa[1].y = fmaf(nl1, r1, bwa[1].y);
        bwa[1].z = fmaf(nl2, r1, bwa[1].z); bwa[1].w = fmaf(nl3, r1, bwa[1].w);
        bwa[2].x = fmaf(nl0, r2, bwa[2].x); bwa[2].y = fmaf(nl1, r2, bwa[2].y);
        bwa[2].z = fmaf(nl2, r2, bwa[2].z); bwa[2].w = fmaf(nl3, r2, bwa[2].w);
        bwa[3].x = fmaf(nl0, r3, bwa[3].x); bwa[3].y = fmaf(nl1, r3, bwa[3].y);
        bwa[3].z = fmaf(nl2, r3, bwa[3].z); bwa[3].w = fmaf(nl3, r3, bwa[3].w);

#pragma unroll
        for (int o = 16; o; o >>= 1) {
            f0 += __shfl_xor_sync(0xffffffffu, f0, o);
            f1 += __shfl_xor_sync(0xffffffffu, f1, o);
            f2 += __shfl_xor_sync(0xffffffffu, f2, o);
            f3 += __shfl_xor_sync(0xffffffffu, f3, o);
        }
        if (lane == 0) {
            fw_s[warp][0][mi] = f0;
            fw_s[warp][1][mi] = f1;
            fw_s[warp][2][mi] = f2;
            fw_s[warp][3][mi] = f3;
        }
    }
    __syncthreads();
    // reduce fw over the 8 warps: 512 outputs, 256 threads
    for (int i = t; i < 512; i += 256) {
        int rr = i >> 7, mi = i & 127;
        float s = 0.0f;
#pragma unroll
        for (int w = 0; w < 8; w++) s += fw_s[w][rr][mi];
        g_fw[(b * 4 + rr) * M + mt * 128 + mi] = s;
    }
    // write bw partials (per-tile, no atomics)
#pragma unroll
    for (int rr = 0; rr < 4; rr++) {
        float4* dst = (float4*)&g_bwp[(((size_t)b * 8 + mt) * 4 + rr) * M + n0];
        *dst = bwa[rr];
    }
}

// ---------------- K7: combine modes (incl. bw partial reduce) + read vectors ----------------
__global__ __launch_bounds__(256) void k_output(float* __restrict__ out) {
    int b = blockIdx.x, t = threadIdx.x;
    __shared__ float nrw_s[4][M];
    for (int idx = t; idx < 4 * M; idx += 256) {
        int rr = idx >> 10, m = idx & 1023;
        float rm0 = g_rm[b * 12 + rr * 3 + 0];
        float rm1 = g_rm[b * 12 + rr * 3 + 1];
        float rm2 = g_rm[b * 12 + rr * 3 + 2];
        float bwv = 0.0f;
#pragma unroll
        for (int mt = 0; mt < 8; mt++)
            bwv += g_bwp[(((size_t)b * 8 + mt) * 4 + rr) * M + m];
        nrw_s[rr][m] = rm0 * bwv
                     + rm1 * g_fw[(b * 4 + rr) * M + m]
                     + rm2 * g_cw[(b * 4 + rr) * M + m];
    }
    __syncthreads();
    int rr = t >> 6, wl = t & 63;
    const float* nmB = g_newmem + (size_t)b * M * W;
    float acc = 0.0f;
#pragma unroll 4
    for (int m = 0; m < M; m++) acc = fmaf(nrw_s[rr][m], nmB[m * W + wl], acc);
    out[(b * 4 + rr) * W + wl] = acc;
}

// ---------------- launch ----------------
extern "C" void kernel_launch(void* const* d_in, const int* in_sizes, int n_in,
                              void* d_out, int out_size) {
    const float* xi   = (const float*)d_in[0];
    const float* Wm   = (const float*)d_in[1];
    const float* bW   = (const float*)d_in[2];
    const float* mem  = (const float*)d_in[3];
    const float* link = (const float*)d_in[4];
    const float* prec = (const float*)d_in[5];
    const float* rw   = (const float*)d_in[6];
    const float* wwo  = (const float*)d_in[7];
    const float* uv   = (const float*)d_in[8];
    float* out = (float*)d_out;

    k_iface<<<B, 512>>>(xi, Wm, bW);
    k_prep<<<B, 512>>>(rw, wwo, uv);
    k_write_content<<<B, 1024>>>(mem);
    k_allocation<<<B, 1024>>>();
    k_memupdate_content<<<B, 1024>>>(mem);
    k_link<<<dim3(8, B), 256>>>(link, prec, rw);
    k_output<<<B, 256>>>(out);
}

// round 4
// speedup vs baseline: 1.5471x; 1.5471x over previous
#include <cuda_runtime.h>
#include <cstdint>
#include <math.h>

// Problem constants
#define B   64
#define M   1024
#define W   64
#define R   4
#define D   512
#define IF  471

// ---------------- scratch (device globals) ----------------
__device__ __align__(16) float g_keys[B * R * W];
__device__ float g_kstr[B * R];
__device__ float g_knorm[B * R];
__device__ __align__(16) float g_wkey[B * W];
__device__ float g_wknorm[B];
__device__ float g_ws[B];
__device__ __align__(16) float g_erase[B * W];
__device__ __align__(16) float g_wvec[B * W];
__device__ float g_ag[B], g_wg[B];
__device__ float g_rm[B * R * 3];
__device__ float g_usage[B * M];
__device__ float g_ww[B * M];
__device__ float g_cw[B * R * M];
__device__ float g_fw[B * R * M];
__device__ __align__(16) float g_bwp[B * 16 * R * M];   // per-mtile bw partials (16.8 MB)
__device__ __align__(16) float g_newmem[B * M * W];

// ---------------- helpers ----------------
__device__ __forceinline__ float sigmoidf_(float x) { return 1.0f / (1.0f + expf(-x)); }
__device__ __forceinline__ float softplusf_(float x) { return (x > 20.0f) ? x : log1pf(expf(x)); }

__device__ __forceinline__ float warpMax_(float v) {
#pragma unroll
    for (int o = 16; o; o >>= 1) v = fmaxf(v, __shfl_xor_sync(0xffffffffu, v, o));
    return v;
}
__device__ __forceinline__ float warpSum_(float v) {
#pragma unroll
    for (int o = 16; o; o >>= 1) v += __shfl_xor_sync(0xffffffffu, v, o);
    return v;
}
__device__ __forceinline__ float blockMax_(float v, float* sh) {
    v = warpMax_(v);
    if ((threadIdx.x & 31) == 0) sh[threadIdx.x >> 5] = v;
    __syncthreads();
    float r = sh[threadIdx.x & 31];
    r = warpMax_(r);
    __syncthreads();
    return r;
}
__device__ __forceinline__ float blockSum_(float v, float* sh) {
    v = warpSum_(v);
    if ((threadIdx.x & 31) == 0) sh[threadIdx.x >> 5] = v;
    __syncthreads();
    float r = sh[threadIdx.x & 31];
    r = warpSum_(r);
    __syncthreads();
    return r;
}

// ---------------- K0: iface GEMV + parse + usage (merged) ----------------
__global__ __launch_bounds__(512) void k_ifprep(const float* __restrict__ xi,
                                                const float* __restrict__ Wm,
                                                const float* __restrict__ bW,
                                                const float* __restrict__ read_weights,
                                                const float* __restrict__ write_weights,
                                                const float* __restrict__ usage_vector) {
    int b = blockIdx.x, t = threadIdx.x;
    __shared__ float xs[D];
    __shared__ float f[IF + 1];
    xs[t] = xi[b * D + t];
    __syncthreads();
    if (t < IF) {
        float acc = bW[t];
#pragma unroll 8
        for (int i = 0; i < D; i++) acc = fmaf(xs[i], Wm[i * IF + t], acc);
        f[t] = acc;
    }
    __syncthreads();

    if (t < 256) g_keys[b * 256 + t] = f[t];
    if (t >= 256 && t < 320) { int i = t - 256; g_wkey[b * W + i] = f[260 + i]; }
    if (t >= 320 && t < 384) { int i = t - 320; g_erase[b * W + i] = sigmoidf_(f[325 + i]); }
    if (t >= 384 && t < 448) { int i = t - 384; g_wvec[b * W + i] = f[389 + i]; }
    if (t < 4) {
        float x = f[256 + t];
        g_kstr[b * 4 + t] = softplusf_(1.0f + fmaxf(x, 0.0f));
        float s = 0.0f;
        for (int i = 0; i < W; i++) { float v = f[t * W + i]; s = fmaf(v, v, s); }
        g_knorm[b * 4 + t] = sqrtf(s);
    }
    if (t == 4) {
        float x = f[324];
        g_ws[b] = softplusf_(1.0f + fmaxf(x, 0.0f));
        float s = 0.0f;
        for (int i = 0; i < W; i++) { float v = f[260 + i]; s = fmaf(v, v, s); }
        g_wknorm[b] = sqrtf(s);
    }
    if (t == 5) g_ag[b] = sigmoidf_(f[457]);
    if (t == 6) g_wg[b] = sigmoidf_(f[458]);
    if (t >= 8 && t < 11) {  // read_modes: softmax over r axis
        int j = t - 8;
        float v[4], mx = -1e30f;
        for (int rr = 0; rr < 4; rr++) { v[rr] = f[458 + rr * 3 + j]; mx = fmaxf(mx, v[rr]); }
        float s = 0.0f;
        for (int rr = 0; rr < 4; rr++) { v[rr] = expf(v[rr] - mx); s += v[rr]; }
        for (int rr = 0; rr < 4; rr++) g_rm[b * 12 + rr * 3 + j] = v[rr] / s;
    }

    float fg[4];
#pragma unroll
    for (int rr = 0; rr < 4; rr++) fg[rr] = sigmoidf_(f[453 + rr]);
    for (int m = t; m < M; m += 512) {
        float uv = usage_vector[b * M + m];
        float wwo = write_weights[b * M + m];
        float u = uv + (1.0f - uv) * wwo;
        float psi = 1.0f;
#pragma unroll
        for (int rr = 0; rr < 4; rr++)
            psi *= (1.0f - fg[rr] * read_weights[(b * 4 + rr) * M + m]);
        g_usage[b * M + m] = u * psi;
    }
}

// ---------------- K1: write-content softmax + allocation sort + ww (merged) ----------------
__global__ __launch_bounds__(1024) void k_weights(const float* __restrict__ memory) {
    int b = blockIdx.x, t = threadIdx.x;
    int lane = t & 31, warp = t >> 5;
    __shared__ float4 key_s[16];
    __shared__ float dv[M];          // content distances -> wc
    __shared__ float red[32];
    __shared__ unsigned long long ks[M];
    __shared__ float wtot[32];

    // ---- write content weighting ----
    if (t < 16) key_s[t] = ((const float4*)(g_wkey + b * W))[t];
    __syncthreads();
    {
        float knorm = g_wknorm[b] + 1e-6f;
        float s = g_ws[b];
        int row = t >> 4, l16 = t & 15;
        const float4* mem4 = (const float4*)(memory + (size_t)b * M * W);
        for (int g = 0; g < 16; g++) {
            int m = g * 64 + row;
            float4 v = mem4[m * 16 + l16];
            float4 k = key_s[l16];
            float dot = v.x * k.x + v.y * k.y + v.z * k.z + v.w * k.w;
            float ns  = v.x * v.x + v.y * v.y + v.z * v.z + v.w * v.w;
#pragma unroll
            for (int o = 8; o; o >>= 1) {
                dot += __shfl_xor_sync(0xffffffffu, dot, o);
                ns  += __shfl_xor_sync(0xffffffffu, ns, o);
            }
            if (l16 == 0) dv[m] = dot * s / ((sqrtf(ns) + 1e-6f) * knorm);
        }
        __syncthreads();
        float x = dv[t];
        float mx = blockMax_(x, red);
        float e = expf(x - mx);
        float sm = blockSum_(e, red);
        __syncthreads();
        dv[t] = e / sm;     // wc
    }

    // ---- allocation: hybrid bitonic sort + warp-scan cumprod ----
    float u = 1e-6f + (1.0f - 1e-6f) * g_usage[b * M + t];
    unsigned long long v = ((unsigned long long)__float_as_uint(u) << 32) | (unsigned)t;
#pragma unroll
    for (int k = 2; k <= 32; k <<= 1) {
#pragma unroll
        for (int j = k >> 1; j > 0; j >>= 1) {
            unsigned long long c = __shfl_xor_sync(0xffffffffu, v, j);
            bool keepMin = ((t & j) == 0) == ((t & k) == 0);
            bool less = v < c;
            v = (less == keepMin) ? v : c;
        }
    }
    ks[t] = v;
    __syncthreads();
#pragma unroll
    for (int k = 64; k <= M; k <<= 1) {
        for (int j = k >> 1; j >= 32; j >>= 1) {
            unsigned long long a = ks[t];
            unsigned long long c = ks[t ^ j];
            bool keepMin = ((t & j) == 0) == ((t & k) == 0);
            bool less = a < c;
            v = (less == keepMin) ? a : c;
            __syncthreads();
            ks[t] = v;
            __syncthreads();
        }
#pragma unroll
        for (int j = 16; j > 0; j >>= 1) {
            unsigned long long c = __shfl_xor_sync(0xffffffffu, v, j);
            bool keepMin = ((t & j) == 0) == ((t & k) == 0);
            bool less = v < c;
            v = (less == keepMin) ? v : c;
        }
        if (k < M) { ks[t] = v; __syncthreads(); }
    }
    float su = __uint_as_float((unsigned)(v >> 32));
    float p = su;
#pragma unroll
    for (int o = 1; o < 32; o <<= 1) {
        float q = __shfl_up_sync(0xffffffffu, p, o);
        if (lane >= o) p *= q;
    }
    if (lane == 31) wtot[warp] = p;
    __syncthreads();
    if (warp == 0) {
        float q = wtot[lane];
#pragma unroll
        for (int o = 1; o < 32; o <<= 1) {
            float rr = __shfl_up_sync(0xffffffffu, q, o);
            if (lane >= o) q *= rr;
        }
        wtot[lane] = q;
    }
    __syncthreads();
    if (warp > 0) p *= wtot[warp - 1];

    int idx = (int)(v & 0xffffffffULL);
    float alloc = (1.0f - su) * p;

    // ---- combine into write weights ----
    float ag = g_ag[b], wg = g_wg[b];
    g_ww[b * M + idx] = wg * (ag * alloc + (1.0f - ag) * dv[idx]);
}

// ---------------- K2: memory update + read content softmax ----------------
__global__ __launch_bounds__(1024) void k_memupdate(const float* __restrict__ memory) {
    int b = blockIdx.x, t = threadIdx.x;
    __shared__ float ww_s[M];
    __shared__ float4 rk_s[4 * 16];
    __shared__ float4 e_s[16], wv_s[16];
    __shared__ float d_s[4][M];
    __shared__ float red[32];

    ww_s[t] = g_ww[b * M + t];
    if (t < 64) rk_s[t] = ((const float4*)(g_keys + b * 256))[t];
    if (t >= 64 && t < 80) e_s[t - 64] = ((const float4*)(g_erase + b * W))[t - 64];
    if (t >= 80 && t < 96) wv_s[t - 80] = ((const float4*)(g_wvec + b * W))[t - 80];
    float kn[4], kstr[4];
#pragma unroll
    for (int rr = 0; rr < 4; rr++) { kn[rr] = g_knorm[b * 4 + rr] + 1e-6f; kstr[rr] = g_kstr[b * 4 + rr]; }
    __syncthreads();

    int row = t >> 4, l16 = t & 15;
    const float4* mem4 = (const float4*)(memory + (size_t)b * M * W);
    float4* nm4 = (float4*)(g_newmem + (size_t)b * M * W);
    for (int g = 0; g < 16; g++) {
        int m = g * 64 + row;
        float wwm = ww_s[m];
        float4 v = mem4[m * 16 + l16];
        float4 e = e_s[l16], wv = wv_s[l16];
        float4 nm;
        nm.x = fmaf(v.x, fmaf(-wwm, e.x, 1.0f), wwm * wv.x);
        nm.y = fmaf(v.y, fmaf(-wwm, e.y, 1.0f), wwm * wv.y);
        nm.z = fmaf(v.z, fmaf(-wwm, e.z, 1.0f), wwm * wv.z);
        nm.w = fmaf(v.w, fmaf(-wwm, e.w, 1.0f), wwm * wv.w);
        nm4[m * 16 + l16] = nm;
        float ns = nm.x * nm.x + nm.y * nm.y + nm.z * nm.z + nm.w * nm.w;
        float dr[4];
#pragma unroll
        for (int rr = 0; rr < 4; rr++) {
            float4 k = rk_s[rr * 16 + l16];
            dr[rr] = nm.x * k.x + nm.y * k.y + nm.z * k.z + nm.w * k.w;
        }
#pragma unroll
        for (int o = 8; o; o >>= 1) {
            ns += __shfl_xor_sync(0xffffffffu, ns, o);
#pragma unroll
            for (int rr = 0; rr < 4; rr++) dr[rr] += __shfl_xor_sync(0xffffffffu, dr[rr], o);
        }
        if (l16 == 0) {
            float inv = 1.0f / (sqrtf(ns) + 1e-6f);
#pragma unroll
            for (int rr = 0; rr < 4; rr++) d_s[rr][m] = dr[rr] * kstr[rr] * inv / kn[rr];
        }
    }
    __syncthreads();
#pragma unroll
    for (int rr = 0; rr < 4; rr++) {
        float x = d_s[rr][t];
        float mx = blockMax_(x, red);
        float e = expf(x - mx);
        float sm = blockSum_(e, red);
        g_cw[(b * 4 + rr) * M + t] = e / sm;
    }
}

// ---------------- K3: fused link-matrix kernel (64-row tiles, packed 6-SHFL reduce) ----------------
__global__ __launch_bounds__(256) void k_link(const float* __restrict__ link,
                                              const float* __restrict__ precedence,
                                              const float* __restrict__ read_weights) {
    int mt = blockIdx.x;   // 16 tiles of 64 rows
    int b  = blockIdx.y;
    int t  = threadIdx.x;
    int warp = t >> 5, lane = t & 31;
    __shared__ __align__(16) float ww_s[M];
    __shared__ __align__(16) float pr_s[M];
    __shared__ __align__(16) float rw_s[4][M];
    __shared__ float fw_s[8][4][64];

    for (int i = t; i < M; i += 256) {
        ww_s[i] = g_ww[b * M + i];
        pr_s[i] = precedence[b * M + i];
    }
    for (int i = t; i < 4 * M; i += 256) ((float*)rw_s)[i] = read_weights[b * 4 * M + i];
    __syncthreads();

    int n0 = t * 4;
    float4 pn  = *(const float4*)&pr_s[n0];
    float4 wwn = *(const float4*)&ww_s[n0];
    float4 rwn[4];
#pragma unroll
    for (int rr = 0; rr < 4; rr++) rwn[rr] = *(const float4*)&rw_s[rr][n0];
    float4 bwa[4];
#pragma unroll
    for (int rr = 0; rr < 4; rr++) bwa[rr] = make_float4(0.f, 0.f, 0.f, 0.f);

    const float4* L4 = (const float4*)(link + (size_t)b * M * M);

#pragma unroll 4
    for (int mi = 0; mi < 64; mi++) {
        int m = mt * 64 + mi;
        float wwm = ww_s[m];
        float cm = 1.0f - wwm;
        float r0 = rw_s[0][m], r1 = rw_s[1][m], r2 = rw_s[2][m], r3 = rw_s[3][m];
        float4 L = L4[(size_t)m * 256 + t];
        float nl0 = fmaf(L.x, cm - wwn.x, wwm * pn.x);
        float nl1 = fmaf(L.y, cm - wwn.y, wwm * pn.y);
        float nl2 = fmaf(L.z, cm - wwn.z, wwm * pn.z);
        float nl3 = fmaf(L.w, cm - wwn.w, wwm * pn.w);
        if (n0 + 0 == m) nl0 = 0.0f;
        if (n0 + 1 == m) nl1 = 0.0f;
        if (n0 + 2 == m) nl2 = 0.0f;
        if (n0 + 3 == m) nl3 = 0.0f;

        float f0 = nl0 * rwn[0].x + nl1 * rwn[0].y + nl2 * rwn[0].z + nl3 * rwn[0].w;
        float f1 = nl0 * rwn[1].x + nl1 * rwn[1].y + nl2 * rwn[1].z + nl3 * rwn[1].w;
        float f2 = nl0 * rwn[2].x + nl1 * rwn[2].y + nl2 * rwn[2].z + nl3 * rwn[2].w;
        float f3 = nl0 * rwn[3].x + nl1 * rwn[3].y + nl2 * rwn[3].z + nl3 * rwn[3].w;

        bwa[0].x = fmaf(nl0, r0, bwa[0].x); bwa[0].y = fmaf(nl1, r0, bwa[0].y);
        bwa[0].z = fmaf(nl2, r0, bwa[0].z); bwa[0].w = fmaf(nl3, r0, bwa[0].w);
        bwa[1].x = fmaf(nl0, r1, bwa[1].x); bwa[1].y = fmaf(nl1, r1, bwa[1].y);
        bwa[1].z = fmaf(nl2, r1, bwa[1].z); bwa[1].w = fmaf(nl3, r1, bwa[1].w);
        bwa[2].x = fmaf(nl0, r2, bwa[2].x); bwa[2].y = fmaf(nl1, r2, bwa[2].y);
        bwa[2].z = fmaf(nl2, r2, bwa[2].z); bwa[2].w = fmaf(nl3, r2, bwa[2].w);
        bwa[3].x = fmaf(nl0, r3, bwa[3].x); bwa[3].y = fmaf(nl1, r3, bwa[3].y);
        bwa[3].z = fmaf(nl2, r3, bwa[3].z); bwa[3].w = fmaf(nl3, r3, bwa[3].w);

        // packed 6-SHFL reduction: lane&3 -> f_{lane&3} summed over warp
        float g01 = (lane & 1) ? f0 : f1;
        g01 = __shfl_xor_sync(0xffffffffu, g01, 1);
        float a01 = ((lane & 1) ? f1 : f0) + g01;
        float g23 = (lane & 1) ? f2 : f3;
        g23 = __shfl_xor_sync(0xffffffffu, g23, 1);
        float a23 = ((lane & 1) ? f3 : f2) + g23;
        float gx = (lane & 2) ? a01 : a23;
        gx = __shfl_xor_sync(0xffffffffu, gx, 2);
        float c = ((lane & 2) ? a23 : a01) + gx;
        c += __shfl_xor_sync(0xffffffffu, c, 4);
        c += __shfl_xor_sync(0xffffffffu, c, 8);
        c += __shfl_xor_sync(0xffffffffu, c, 16);
        if (lane < 4) fw_s[warp][lane][mi] = c;
    }
    __syncthreads();
    // reduce fw over the 8 warps: 256 outputs, 256 threads
    {
        int rr = t >> 6, mi = t & 63;
        float s = 0.0f;
#pragma unroll
        for (int w = 0; w < 8; w++) s += fw_s[w][rr][mi];
        g_fw[(b * 4 + rr) * M + mt * 64 + mi] = s;
    }
    // write bw partials (per-tile, no atomics)
#pragma unroll
    for (int rr = 0; rr < 4; rr++) {
        float4* dst = (float4*)&g_bwp[(((size_t)b * 16 + mt) * 4 + rr) * M + n0];
        *dst = bwa[rr];
    }
}

// ---------------- K4: combine modes + read vectors ----------------
__global__ __launch_bounds__(256) void k_output(float* __restrict__ out) {
    int b = blockIdx.x, t = threadIdx.x;
    __shared__ float nrw_s[4][M];
    for (int idx = t; idx < 4 * M; idx += 256) {
        int rr = idx >> 10, m = idx & 1023;
        float rm0 = g_rm[b * 12 + rr * 3 + 0];
        float rm1 = g_rm[b * 12 + rr * 3 + 1];
        float rm2 = g_rm[b * 12 + rr * 3 + 2];
        float bwv = 0.0f;
#pragma unroll
        for (int mt = 0; mt < 16; mt++)
            bwv += g_bwp[(((size_t)b * 16 + mt) * 4 + rr) * M + m];
        nrw_s[rr][m] = rm0 * bwv
                     + rm1 * g_fw[(b * 4 + rr) * M + m]
                     + rm2 * g_cw[(b * 4 + rr) * M + m];
    }
    __syncthreads();
    int rr = t >> 6, wl = t & 63;
    const float* nmB = g_newmem + (size_t)b * M * W;
    float acc = 0.0f;
#pragma unroll 8
    for (int m = 0; m < M; m++) acc = fmaf(nrw_s[rr][m], nmB[m * W + wl], acc);
    out[(b * 4 + rr) * W + wl] = acc;
}

// ---------------- launch ----------------
extern "C" void kernel_launch(void* const* d_in, const int* in_sizes, int n_in,
                              void* d_out, int out_size) {
    const float* xi   = (const float*)d_in[0];
    const float* Wm   = (const float*)d_in[1];
    const float* bW   = (const float*)d_in[2];
    const float* mem  = (const float*)d_in[3];
    const float* link = (const float*)d_in[4];
    const float* prec = (const float*)d_in[5];
    const float* rw   = (const float*)d_in[6];
    const float* wwo  = (const float*)d_in[7];
    const float* uv   = (const float*)d_in[8];
    float* out = (float*)d_out;

    k_ifprep<<<B, 512>>>(xi, Wm, bW, rw, wwo, uv);
    k_weights<<<B, 1024>>>(mem);
    k_memupdate<<<B, 1024>>>(mem);
    k_link<<<dim3(16, B), 256>>>(link, prec, rw);   // launch #4 -> ncu capture slot
    k_output<<<B, 256>>>(out);
}

// round 6
// speedup vs baseline: 1.7523x; 1.1326x over previous
#include <cuda_runtime.h>
#include <cstdint>
#include <math.h>

// Problem constants
#define B   64
#define M   1024
#define W   64
#define R   4
#define D   512
#define IF  471

// ---------------- scratch (device globals) ----------------
__device__ __align__(16) float g_keys[B * R * W];
__device__ float g_kstr[B * R];
__device__ float g_knorm[B * R];
__device__ __align__(16) float g_wkey[B * W];
__device__ float g_wknorm[B];
__device__ float g_ws[B];
__device__ __align__(16) float g_erase[B * W];
__device__ __align__(16) float g_wvec[B * W];
__device__ float g_ag[B], g_wg[B];
__device__ float g_rm[B * R * 3];
__device__ float g_usage[B * M];
__device__ float g_ww[B * M];
__device__ float g_d[B * R * M];        // content distances (pre-softmax)
__device__ float g_cw[B * R * M];
__device__ __align__(16) float g_fwp[B * 2 * R * M];    // fw partials over 2 col-halves (2MB)
__device__ __align__(16) float g_bwp[B * 16 * R * M];   // bw partials over 16 row-tiles (16.8MB)
__device__ float g_nrw[B * R * M];
__device__ __align__(16) float g_newmem[B * M * W];

// ---------------- helpers ----------------
__device__ __forceinline__ float sigmoidf_(float x) { return 1.0f / (1.0f + expf(-x)); }
__device__ __forceinline__ float softplusf_(float x) { return (x > 20.0f) ? x : log1pf(expf(x)); }

__device__ __forceinline__ float warpMax_(float v) {
#pragma unroll
    for (int o = 16; o; o >>= 1) v = fmaxf(v, __shfl_xor_sync(0xffffffffu, v, o));
    return v;
}
__device__ __forceinline__ float warpSum_(float v) {
#pragma unroll
    for (int o = 16; o; o >>= 1) v += __shfl_xor_sync(0xffffffffu, v, o);
    return v;
}
__device__ __forceinline__ float blockMax_(float v, float* sh) {
    v = warpMax_(v);
    if ((threadIdx.x & 31) == 0) sh[threadIdx.x >> 5] = v;
    __syncthreads();
    float r = sh[threadIdx.x & 31];
    r = warpMax_(r);
    __syncthreads();
    return r;
}
__device__ __forceinline__ float blockSum_(float v, float* sh) {
    v = warpSum_(v);
    if ((threadIdx.x & 31) == 0) sh[threadIdx.x >> 5] = v;
    __syncthreads();
    float r = sh[threadIdx.x & 31];
    r = warpSum_(r);
    __syncthreads();
    return r;
}

// ---------------- K1: iface GEMV + parse + usage ----------------
__global__ __launch_bounds__(512) void k_ifprep(const float* __restrict__ xi,
                                                const float* __restrict__ Wm,
                                                const float* __restrict__ bW,
                                                const float* __restrict__ read_weights,
                                                const float* __restrict__ write_weights,
                                                const float* __restrict__ usage_vector) {
    int b = blockIdx.x, t = threadIdx.x;
    __shared__ float xs[D];
    __shared__ float f[IF + 1];
    xs[t] = xi[b * D + t];
    __syncthreads();
    if (t < IF) {
        float acc = bW[t];
#pragma unroll 8
        for (int i = 0; i < D; i++) acc = fmaf(xs[i], Wm[i * IF + t], acc);
        f[t] = acc;
    }
    __syncthreads();

    if (t < 256) g_keys[b * 256 + t] = f[t];
    if (t >= 256 && t < 320) { int i = t - 256; g_wkey[b * W + i] = f[260 + i]; }
    if (t >= 320 && t < 384) { int i = t - 320; g_erase[b * W + i] = sigmoidf_(f[325 + i]); }
    if (t >= 384 && t < 448) { int i = t - 384; g_wvec[b * W + i] = f[389 + i]; }
    if (t < 4) {
        float x = f[256 + t];
        g_kstr[b * 4 + t] = softplusf_(1.0f + fmaxf(x, 0.0f));
        float s = 0.0f;
        for (int i = 0; i < W; i++) { float v = f[t * W + i]; s = fmaf(v, v, s); }
        g_knorm[b * 4 + t] = sqrtf(s);
    }
    if (t == 4) {
        float x = f[324];
        g_ws[b] = softplusf_(1.0f + fmaxf(x, 0.0f));
        float s = 0.0f;
        for (int i = 0; i < W; i++) { float v = f[260 + i]; s = fmaf(v, v, s); }
        g_wknorm[b] = sqrtf(s);
    }
    if (t == 5) g_ag[b] = sigmoidf_(f[457]);
    if (t == 6) g_wg[b] = sigmoidf_(f[458]);
    if (t >= 8 && t < 11) {  // read_modes: softmax over r axis
        int j = t - 8;
        float v[4], mx = -1e30f;
        for (int rr = 0; rr < 4; rr++) { v[rr] = f[458 + rr * 3 + j]; mx = fmaxf(mx, v[rr]); }
        float s = 0.0f;
        for (int rr = 0; rr < 4; rr++) { v[rr] = expf(v[rr] - mx); s += v[rr]; }
        for (int rr = 0; rr < 4; rr++) g_rm[b * 12 + rr * 3 + j] = v[rr] / s;
    }

    float fg[4];
#pragma unroll
    for (int rr = 0; rr < 4; rr++) fg[rr] = sigmoidf_(f[453 + rr]);
    for (int m = t; m < M; m += 512) {
        float uv = usage_vector[b * M + m];
        float wwo = write_weights[b * M + m];
        float u = uv + (1.0f - uv) * wwo;
        float psi = 1.0f;
#pragma unroll
        for (int rr = 0; rr < 4; rr++)
            psi *= (1.0f - fg[rr] * read_weights[(b * 4 + rr) * M + m]);
        g_usage[b * M + m] = u * psi;
    }
}

// ---------------- K2: write-content softmax + allocation sort + ww ----------------
__global__ __launch_bounds__(1024) void k_weights(const float* __restrict__ memory) {
    int b = blockIdx.x, t = threadIdx.x;
    int lane = t & 31, warp = t >> 5;
    __shared__ float4 key_s[16];
    __shared__ float dv[M];
    __shared__ float red[32];
    __shared__ unsigned long long ks[M];
    __shared__ float wtot[32];

    if (t < 16) key_s[t] = ((const float4*)(g_wkey + b * W))[t];
    __syncthreads();
    {
        float knorm = g_wknorm[b] + 1e-6f;
        float s = g_ws[b];
        int row = t >> 4, l16 = t & 15;
        const float4* mem4 = (const float4*)(memory + (size_t)b * M * W);
        for (int g = 0; g < 16; g++) {
            int m = g * 64 + row;
            float4 v = mem4[m * 16 + l16];
            float4 k = key_s[l16];
            float dot = v.x * k.x + v.y * k.y + v.z * k.z + v.w * k.w;
            float ns  = v.x * v.x + v.y * v.y + v.z * v.z + v.w * v.w;
#pragma unroll
            for (int o = 8; o; o >>= 1) {
                dot += __shfl_xor_sync(0xffffffffu, dot, o);
                ns  += __shfl_xor_sync(0xffffffffu, ns, o);
            }
            if (l16 == 0) dv[m] = dot * s / ((sqrtf(ns) + 1e-6f) * knorm);
        }
        __syncthreads();
        float x = dv[t];
        float mx = blockMax_(x, red);
        float e = expf(x - mx);
        float sm = blockSum_(e, red);
        __syncthreads();
        dv[t] = e / sm;
    }

    // allocation: hybrid bitonic sort + warp-scan cumprod
    float u = 1e-6f + (1.0f - 1e-6f) * g_usage[b * M + t];
    unsigned long long v = ((unsigned long long)__float_as_uint(u) << 32) | (unsigned)t;
#pragma unroll
    for (int k = 2; k <= 32; k <<= 1) {
#pragma unroll
        for (int j = k >> 1; j > 0; j >>= 1) {
            unsigned long long c = __shfl_xor_sync(0xffffffffu, v, j);
            bool keepMin = ((t & j) == 0) == ((t & k) == 0);
            bool less = v < c;
            v = (less == keepMin) ? v : c;
        }
    }
    ks[t] = v;
    __syncthreads();
#pragma unroll
    for (int k = 64; k <= M; k <<= 1) {
        for (int j = k >> 1; j >= 32; j >>= 1) {
            unsigned long long a = ks[t];
            unsigned long long c = ks[t ^ j];
            bool keepMin = ((t & j) == 0) == ((t & k) == 0);
            bool less = a < c;
            v = (less == keepMin) ? a : c;
            __syncthreads();
            ks[t] = v;
            __syncthreads();
        }
#pragma unroll
        for (int j = 16; j > 0; j >>= 1) {
            unsigned long long c = __shfl_xor_sync(0xffffffffu, v, j);
            bool keepMin = ((t & j) == 0) == ((t & k) == 0);
            bool less = v < c;
            v = (less == keepMin) ? v : c;
        }
        if (k < M) { ks[t] = v; __syncthreads(); }
    }
    float su = __uint_as_float((unsigned)(v >> 32));
    float p = su;
#pragma unroll
    for (int o = 1; o < 32; o <<= 1) {
        float q = __shfl_up_sync(0xffffffffu, p, o);
        if (lane >= o) p *= q;
    }
    if (lane == 31) wtot[warp] = p;
    __syncthreads();
    if (warp == 0) {
        float q = wtot[lane];
#pragma unroll
        for (int o = 1; o < 32; o <<= 1) {
            float rr = __shfl_up_sync(0xffffffffu, q, o);
            if (lane >= o) q *= rr;
        }
        wtot[lane] = q;
    }
    __syncthreads();
    if (warp > 0) p *= wtot[warp - 1];

    int idx = (int)(v & 0xffffffffULL);
    float alloc = (1.0f - su) * p;
    float ag = g_ag[b], wg = g_wg[b];
    g_ww[b * M + idx] = wg * (ag * alloc + (1.0f - ag) * dv[idx]);
}

// ---------------- K3: link kernel v3 (2 cols/thread, high occupancy) ----------------
// G[m,n] = (1-ww[m]-ww[n])*L[m,n] + ww[m]*p[n]  (diagonal NOT zeroed; corrected in k_nrw)
__global__ __launch_bounds__(256) void k_link(const float* __restrict__ link,
                                              const float* __restrict__ precedence,
                                              const float* __restrict__ read_weights) {
    int mt = blockIdx.x;   // 0..15 (64-row tiles)
    int nt = blockIdx.y;   // 0..1  (512-col halves)
    int b  = blockIdx.z;
    int t  = threadIdx.x;
    int warp = t >> 5, lane = t & 31;
    __shared__ float ww_row[64];
    __shared__ __align__(16) float4 rw_row[64];
    __shared__ float fw_s[8][4][64];

    if (t < 64) ww_row[t] = g_ww[b * M + mt * 64 + t];
    {
        int r = t >> 6, mi = t & 63;
        ((float*)rw_row)[mi * 4 + r] = read_weights[(b * 4 + r) * M + mt * 64 + mi];
    }

    int n0 = nt * 512 + t * 2;
    float2 wwn = *(const float2*)&g_ww[b * M + n0];
    float2 pn  = *(const float2*)&precedence[b * M + n0];
    float2 rwn0 = *(const float2*)&read_weights[(b * 4 + 0) * M + n0];
    float2 rwn1 = *(const float2*)&read_weights[(b * 4 + 1) * M + n0];
    float2 rwn2 = *(const float2*)&read_weights[(b * 4 + 2) * M + n0];
    float2 rwn3 = *(const float2*)&read_weights[(b * 4 + 3) * M + n0];
    float ax = 1.0f - wwn.x, ay = 1.0f - wwn.y;
    float2 bw0 = {0,0}, bw1 = {0,0}, bw2 = {0,0}, bw3 = {0,0};

    const float2* Lp = (const float2*)(link + (size_t)b * M * M + (size_t)(mt * 64) * M) + (n0 >> 1);
    __syncthreads();

#pragma unroll 4
    for (int mi = 0; mi < 64; mi++) {
        float wwm = ww_row[mi];
        float4 rr4 = rw_row[mi];
        float2 L = *Lp; Lp += (M / 2);
        float nl0 = fmaf(L.x, ax - wwm, wwm * pn.x);
        float nl1 = fmaf(L.y, ay - wwm, wwm * pn.y);

        float f0 = fmaf(nl1, rwn0.y, nl0 * rwn0.x);
        float f1 = fmaf(nl1, rwn1.y, nl0 * rwn1.x);
        float f2 = fmaf(nl1, rwn2.y, nl0 * rwn2.x);
        float f3 = fmaf(nl1, rwn3.y, nl0 * rwn3.x);

        bw0.x = fmaf(nl0, rr4.x, bw0.x); bw0.y = fmaf(nl1, rr4.x, bw0.y);
        bw1.x = fmaf(nl0, rr4.y, bw1.x); bw1.y = fmaf(nl1, rr4.y, bw1.y);
        bw2.x = fmaf(nl0, rr4.z, bw2.x); bw2.y = fmaf(nl1, rr4.z, bw2.y);
        bw3.x = fmaf(nl0, rr4.w, bw3.x); bw3.y = fmaf(nl1, rr4.w, bw3.y);

        // packed 6-SHFL reduction: lane L ends with f_{L&3} summed over warp
        float g01 = (lane & 1) ? f0 : f1;
        g01 = __shfl_xor_sync(0xffffffffu, g01, 1);
        float a01 = ((lane & 1) ? f1 : f0) + g01;
        float g23 = (lane & 1) ? f2 : f3;
        g23 = __shfl_xor_sync(0xffffffffu, g23, 1);
        float a23 = ((lane & 1) ? f3 : f2) + g23;
        float gx = (lane & 2) ? a01 : a23;
        gx = __shfl_xor_sync(0xffffffffu, gx, 2);
        float c = ((lane & 2) ? a23 : a01) + gx;
        c += __shfl_xor_sync(0xffffffffu, c, 4);
        c += __shfl_xor_sync(0xffffffffu, c, 8);
        c += __shfl_xor_sync(0xffffffffu, c, 16);
        if (lane < 4) fw_s[warp][lane][mi] = c;
    }
    __syncthreads();
    {
        int rr = t >> 6, mi = t & 63;
        float s = 0.0f;
#pragma unroll
        for (int w = 0; w < 8; w++) s += fw_s[w][rr][mi];
        g_fwp[((b * 2 + nt) * 4 + rr) * M + mt * 64 + mi] = s;
    }
    *(float2*)&g_bwp[((b * 16 + mt) * 4 + 0) * M + n0] = bw0;
    *(float2*)&g_bwp[((b * 16 + mt) * 4 + 1) * M + n0] = bw1;
    *(float2*)&g_bwp[((b * 16 + mt) * 4 + 2) * M + n0] = bw2;
    *(float2*)&g_bwp[((b * 16 + mt) * 4 + 3) * M + n0] = bw3;
}

// ---------------- K4: memory update + content distances (grid 8x64) [PROFILED] ----------------
__global__ __launch_bounds__(256) void k_memup(const float* __restrict__ memory) {
    int slab = blockIdx.x, b = blockIdx.y, t = threadIdx.x;
    __shared__ float ww_s[128];
    __shared__ float4 rk_s[64];
    __shared__ float4 e_s[16], wv_s[16];
    __shared__ float sk_s[4];

    if (t < 128) ww_s[t] = g_ww[b * M + slab * 128 + t];
    if (t >= 128 && t < 192) rk_s[t - 128] = ((const float4*)(g_keys + b * 256))[t - 128];
    if (t >= 192 && t < 208) e_s[t - 192] = ((const float4*)(g_erase + b * W))[t - 192];
    if (t >= 208 && t < 224) wv_s[t - 208] = ((const float4*)(g_wvec + b * W))[t - 208];
    if (t >= 224 && t < 228) {
        int r = t - 224;
        sk_s[r] = g_kstr[b * 4 + r] / (g_knorm[b * 4 + r] + 1e-6f);
    }
    __syncthreads();

    int row16 = t >> 4, l16 = t & 15;
    const float4* mem4 = (const float4*)(memory + (size_t)b * M * W);
    float4* nm4 = (float4*)(g_newmem + (size_t)b * M * W);
#pragma unroll 2
    for (int pass = 0; pass < 8; pass++) {
        int mi = pass * 16 + row16;
        int m = slab * 128 + mi;
        float wwm = ww_s[mi];
        float4 v = mem4[m * 16 + l16];
        float4 e = e_s[l16], wv = wv_s[l16];
        float4 nm;
        nm.x = fmaf(v.x, fmaf(-wwm, e.x, 1.0f), wwm * wv.x);
        nm.y = fmaf(v.y, fmaf(-wwm, e.y, 1.0f), wwm * wv.y);
        nm.z = fmaf(v.z, fmaf(-wwm, e.z, 1.0f), wwm * wv.z);
        nm.w = fmaf(v.w, fmaf(-wwm, e.w, 1.0f), wwm * wv.w);
        nm4[m * 16 + l16] = nm;
        float ns = nm.x * nm.x + nm.y * nm.y + nm.z * nm.z + nm.w * nm.w;
        float dr0, dr1, dr2, dr3;
        {
            float4 k0 = rk_s[0 * 16 + l16], k1 = rk_s[1 * 16 + l16];
            float4 k2 = rk_s[2 * 16 + l16], k3 = rk_s[3 * 16 + l16];
            dr0 = nm.x * k0.x + nm.y * k0.y + nm.z * k0.z + nm.w * k0.w;
            dr1 = nm.x * k1.x + nm.y * k1.y + nm.z * k1.z + nm.w * k1.w;
            dr2 = nm.x * k2.x + nm.y * k2.y + nm.z * k2.z + nm.w * k2.w;
            dr3 = nm.x * k3.x + nm.y * k3.y + nm.z * k3.z + nm.w * k3.w;
        }
        // packed reduce of dr0..dr3 over the 16-lane group (xor 1,2,4,8)
        float g01 = (l16 & 1) ? dr0 : dr1;
        g01 = __shfl_xor_sync(0xffffffffu, g01, 1);
        float a01 = ((l16 & 1) ? dr1 : dr0) + g01;
        float g23 = (l16 & 1) ? dr2 : dr3;
        g23 = __shfl_xor_sync(0xffffffffu, g23, 1);
        float a23 = ((l16 & 1) ? dr3 : dr2) + g23;
        float gx = (l16 & 2) ? a01 : a23;
        gx = __shfl_xor_sync(0xffffffffu, gx, 2);
        float c = ((l16 & 2) ? a23 : a01) + gx;
        c += __shfl_xor_sync(0xffffffffu, c, 4);
        c += __shfl_xor_sync(0xffffffffu, c, 8);
#pragma unroll
        for (int o = 8; o; o >>= 1) ns += __shfl_xor_sync(0xffffffffu, ns, o);
        if (l16 < 4) {
            float inv = 1.0f / (sqrtf(ns) + 1e-6f);
            g_d[(b * 4 + l16) * M + m] = c * sk_s[l16] * inv;
        }
    }
}

// ---------------- K5: read-content softmax ----------------
__global__ __launch_bounds__(1024) void k_cwsm() {
    int b = blockIdx.x, t = threadIdx.x;
    __shared__ float red[32];
#pragma unroll
    for (int rr = 0; rr < 4; rr++) {
        float x = g_d[(b * 4 + rr) * M + t];
        float mx = blockMax_(x, red);
        float e = expf(x - mx);
        float sm = blockSum_(e, red);
        g_cw[(b * 4 + rr) * M + t] = e / sm;
    }
}

// ---------------- K6: reduce partials + diag correction + mode combine ----------------
__global__ __launch_bounds__(512) void k_nrw(const float* __restrict__ link,
                                             const float* __restrict__ precedence,
                                             const float* __restrict__ read_weights) {
    int bx = blockIdx.x, b = blockIdx.y, t = threadIdx.x;
    int rr = t >> 7, mi = t & 127;
    int m = bx * 128 + mi;

    float fw = g_fwp[((b * 2 + 0) * 4 + rr) * M + m] + g_fwp[((b * 2 + 1) * 4 + rr) * M + m];
    float bw = 0.0f;
#pragma unroll
    for (int mt = 0; mt < 16; mt++)
        bw += g_bwp[((b * 16 + mt) * 4 + rr) * M + m];

    float wwm = g_ww[b * M + m];
    float pm  = precedence[b * M + m];
    float rwv = read_weights[(b * 4 + rr) * M + m];
    float Ld  = link[(size_t)b * M * M + (size_t)m * (M + 1)];
    float nld = fmaf(1.0f - 2.0f * wwm, Ld, wwm * pm);
    float corr = nld * rwv;
    fw -= corr;
    bw -= corr;

    float rm0 = g_rm[b * 12 + rr * 3 + 0];
    float rm1 = g_rm[b * 12 + rr * 3 + 1];
    float rm2 = g_rm[b * 12 + rr * 3 + 2];
    g_nrw[(b * 4 + rr) * M + m] = rm0 * bw + rm1 * fw + rm2 * g_cw[(b * 4 + rr) * M + m];
}

// ---------------- K7: read vectors GEMV ----------------
__global__ __launch_bounds__(256) void k_gemv(float* __restrict__ out) {
    int b = blockIdx.x, t = threadIdx.x;
    __shared__ float nrw_s[4 * M];
    for (int i = t; i < 4 * M; i += 256) nrw_s[i] = g_nrw[b * 4 * M + i];
    __syncthreads();
    int rr = t >> 6, wl = t & 63;
    const float* nmB = g_newmem + (size_t)b * M * W;
    const float* nr = nrw_s + rr * M;
    float acc = 0.0f;
#pragma unroll 8
    for (int m = 0; m < M; m++) acc = fmaf(nr[m], nmB[m * W + wl], acc);
    out[(b * 4 + rr) * W + wl] = acc;
}

// ---------------- launch ----------------
extern "C" void kernel_launch(void* const* d_in, const int* in_sizes, int n_in,
                              void* d_out, int out_size) {
    const float* xi   = (const float*)d_in[0];
    const float* Wm   = (const float*)d_in[1];
    const float* bW   = (const float*)d_in[2];
    const float* mem  = (const float*)d_in[3];
    const float* link = (const float*)d_in[4];
    const float* prec = (const float*)d_in[5];
    const float* rw   = (const float*)d_in[6];
    const float* wwo  = (const float*)d_in[7];
    const float* uv   = (const float*)d_in[8];
    float* out = (float*)d_out;

    k_ifprep<<<B, 512>>>(xi, Wm, bW, rw, wwo, uv);       // 1
    k_weights<<<B, 1024>>>(mem);                          // 2
    k_link<<<dim3(16, 2, B), 256>>>(link, prec, rw);      // 3
    k_memup<<<dim3(8, B), 256>>>(mem);                    // 4  <- ncu capture slot
    k_cwsm<<<B, 1024>>>();                                // 5
    k_nrw<<<dim3(8, B), 512>>>(link, prec, rw);           // 6
    k_gemv<<<B, 256>>>(out);                              // 7
}

// round 7
// speedup vs baseline: 1.9499x; 1.1128x over previous
#include <cuda_runtime.h>
#include <cstdint>
#include <math.h>

// Problem constants
#define B   64
#define M   1024
#define W   64
#define R   4
#define D   512
#define IF  471

// ---------------- scratch (device globals) ----------------
__device__ __align__(16) float g_keys[B * R * W];
__device__ float g_kstr[B * R];
__device__ float g_knorm[B * R];
__device__ __align__(16) float g_wkey[B * W];
__device__ float g_wknorm[B];
__device__ float g_ws[B];
__device__ __align__(16) float g_erase[B * W];
__device__ __align__(16) float g_wvec[B * W];
__device__ float g_ag[B], g_wg[B];
__device__ float g_rm[B * R * 3];
__device__ float g_usage[B * M];
__device__ float g_ww[B * M];
__device__ float g_d[B * R * M];
__device__ float g_cw[B * R * M];
__device__ __align__(16) float g_fwp[B * 2 * R * M];
__device__ __align__(16) float g_bwp[B * 16 * R * M];
__device__ float g_nrw[B * R * M];
__device__ __align__(16) float g_newmem[B * M * W];

// ---------------- helpers ----------------
__device__ __forceinline__ float sigmoidf_(float x) { return 1.0f / (1.0f + expf(-x)); }
__device__ __forceinline__ float softplusf_(float x) { return (x > 20.0f) ? x : log1pf(expf(x)); }

__device__ __forceinline__ float warpMax_(float v) {
#pragma unroll
    for (int o = 16; o; o >>= 1) v = fmaxf(v, __shfl_xor_sync(0xffffffffu, v, o));
    return v;
}
__device__ __forceinline__ float warpSum_(float v) {
#pragma unroll
    for (int o = 16; o; o >>= 1) v += __shfl_xor_sync(0xffffffffu, v, o);
    return v;
}
__device__ __forceinline__ float blockMax_(float v, float* sh) {
    v = warpMax_(v);
    if ((threadIdx.x & 31) == 0) sh[threadIdx.x >> 5] = v;
    __syncthreads();
    float r = sh[threadIdx.x & 31];
    r = warpMax_(r);
    __syncthreads();
    return r;
}
__device__ __forceinline__ float blockSum_(float v, float* sh) {
    v = warpSum_(v);
    if ((threadIdx.x & 31) == 0) sh[threadIdx.x >> 5] = v;
    __syncthreads();
    float r = sh[threadIdx.x & 31];
    r = warpSum_(r);
    __syncthreads();
    return r;
}

// ---------------- K1: iface GEMV + parse + usage ----------------
__global__ __launch_bounds__(512) void k_ifprep(const float* __restrict__ xi,
                                                const float* __restrict__ Wm,
                                                const float* __restrict__ bW,
                                                const float* __restrict__ read_weights,
                                                const float* __restrict__ write_weights,
                                                const float* __restrict__ usage_vector) {
    int b = blockIdx.x, t = threadIdx.x;
    __shared__ float xs[D];
    __shared__ float f[IF + 1];
    xs[t] = xi[b * D + t];
    __syncthreads();
    if (t < IF) {
        float acc = bW[t];
#pragma unroll 8
        for (int i = 0; i < D; i++) acc = fmaf(xs[i], Wm[i * IF + t], acc);
        f[t] = acc;
    }
    __syncthreads();

    if (t < 256) g_keys[b * 256 + t] = f[t];
    if (t >= 256 && t < 320) { int i = t - 256; g_wkey[b * W + i] = f[260 + i]; }
    if (t >= 320 && t < 384) { int i = t - 320; g_erase[b * W + i] = sigmoidf_(f[325 + i]); }
    if (t >= 384 && t < 448) { int i = t - 384; g_wvec[b * W + i] = f[389 + i]; }
    if (t < 4) {
        float x = f[256 + t];
        g_kstr[b * 4 + t] = softplusf_(1.0f + fmaxf(x, 0.0f));
        float s = 0.0f;
        for (int i = 0; i < W; i++) { float v = f[t * W + i]; s = fmaf(v, v, s); }
        g_knorm[b * 4 + t] = sqrtf(s);
    }
    if (t == 4) {
        float x = f[324];
        g_ws[b] = softplusf_(1.0f + fmaxf(x, 0.0f));
        float s = 0.0f;
        for (int i = 0; i < W; i++) { float v = f[260 + i]; s = fmaf(v, v, s); }
        g_wknorm[b] = sqrtf(s);
    }
    if (t == 5) g_ag[b] = sigmoidf_(f[457]);
    if (t == 6) g_wg[b] = sigmoidf_(f[458]);
    if (t >= 8 && t < 11) {  // read_modes: softmax over r axis
        int j = t - 8;
        float v[4], mx = -1e30f;
        for (int rr = 0; rr < 4; rr++) { v[rr] = f[458 + rr * 3 + j]; mx = fmaxf(mx, v[rr]); }
        float s = 0.0f;
        for (int rr = 0; rr < 4; rr++) { v[rr] = expf(v[rr] - mx); s += v[rr]; }
        for (int rr = 0; rr < 4; rr++) g_rm[b * 12 + rr * 3 + j] = v[rr] / s;
    }

    float fg[4];
#pragma unroll
    for (int rr = 0; rr < 4; rr++) fg[rr] = sigmoidf_(f[453 + rr]);
    for (int m = t; m < M; m += 512) {
        float uv = usage_vector[b * M + m];
        float wwo = write_weights[b * M + m];
        float u = uv + (1.0f - uv) * wwo;
        float psi = 1.0f;
#pragma unroll
        for (int rr = 0; rr < 4; rr++)
            psi *= (1.0f - fg[rr] * read_weights[(b * 4 + rr) * M + m]);
        g_usage[b * M + m] = u * psi;
    }
}

// ---------------- K2: write-content softmax + allocation sort + ww ----------------
__global__ __launch_bounds__(1024) void k_weights(const float* __restrict__ memory) {
    int b = blockIdx.x, t = threadIdx.x;
    int lane = t & 31, warp = t >> 5;
    __shared__ float4 key_s[16];
    __shared__ float dv[M];
    __shared__ float red[32];
    __shared__ unsigned long long ks[M];
    __shared__ float wtot[32];

    if (t < 16) key_s[t] = ((const float4*)(g_wkey + b * W))[t];
    __syncthreads();
    {
        float knorm = g_wknorm[b] + 1e-6f;
        float s = g_ws[b];
        int row = t >> 4, l16 = t & 15;
        const float4* mem4 = (const float4*)(memory + (size_t)b * M * W);
        for (int g = 0; g < 16; g++) {
            int m = g * 64 + row;
            float4 v = mem4[m * 16 + l16];
            float4 k = key_s[l16];
            float dot = v.x * k.x + v.y * k.y + v.z * k.z + v.w * k.w;
            float ns  = v.x * v.x + v.y * v.y + v.z * v.z + v.w * v.w;
#pragma unroll
            for (int o = 8; o; o >>= 1) {
                dot += __shfl_xor_sync(0xffffffffu, dot, o);
                ns  += __shfl_xor_sync(0xffffffffu, ns, o);
            }
            if (l16 == 0) dv[m] = dot * s / ((sqrtf(ns) + 1e-6f) * knorm);
        }
        __syncthreads();
        float x = dv[t];
        float mx = blockMax_(x, red);
        float e = expf(x - mx);
        float sm = blockSum_(e, red);
        __syncthreads();
        dv[t] = e / sm;
    }

    // allocation: hybrid bitonic sort + warp-scan cumprod
    float u = 1e-6f + (1.0f - 1e-6f) * g_usage[b * M + t];
    unsigned long long v = ((unsigned long long)__float_as_uint(u) << 32) | (unsigned)t;
#pragma unroll
    for (int k = 2; k <= 32; k <<= 1) {
#pragma unroll
        for (int j = k >> 1; j > 0; j >>= 1) {
            unsigned long long c = __shfl_xor_sync(0xffffffffu, v, j);
            bool keepMin = ((t & j) == 0) == ((t & k) == 0);
            bool less = v < c;
            v = (less == keepMin) ? v : c;
        }
    }
    ks[t] = v;
    __syncthreads();
#pragma unroll
    for (int k = 64; k <= M; k <<= 1) {
        for (int j = k >> 1; j >= 32; j >>= 1) {
            unsigned long long a = ks[t];
            unsigned long long c = ks[t ^ j];
            bool keepMin = ((t & j) == 0) == ((t & k) == 0);
            bool less = a < c;
            v = (less == keepMin) ? a : c;
            __syncthreads();
            ks[t] = v;
            __syncthreads();
        }
#pragma unroll
        for (int j = 16; j > 0; j >>= 1) {
            unsigned long long c = __shfl_xor_sync(0xffffffffu, v, j);
            bool keepMin = ((t & j) == 0) == ((t & k) == 0);
            bool less = v < c;
            v = (less == keepMin) ? v : c;
        }
        if (k < M) { ks[t] = v; __syncthreads(); }
    }
    float su = __uint_as_float((unsigned)(v >> 32));
    float p = su;
#pragma unroll
    for (int o = 1; o < 32; o <<= 1) {
        float q = __shfl_up_sync(0xffffffffu, p, o);
        if (lane >= o) p *= q;
    }
    if (lane == 31) wtot[warp] = p;
    __syncthreads();
    if (warp == 0) {
        float q = wtot[lane];
#pragma unroll
        for (int o = 1; o < 32; o <<= 1) {
            float rr = __shfl_up_sync(0xffffffffu, q, o);
            if (lane >= o) q *= rr;
        }
        wtot[lane] = q;
    }
    __syncthreads();
    if (warp > 0) p *= wtot[warp - 1];

    int idx = (int)(v & 0xffffffffULL);
    float alloc = (1.0f - su) * p;
    float ag = g_ag[b], wg = g_wg[b];
    g_ww[b * M + idx] = wg * (ag * alloc + (1.0f - ag) * dv[idx]);
}

// ---------------- K3: memory update + content distances (grid 8x64) ----------------
__global__ __launch_bounds__(256) void k_memup(const float* __restrict__ memory) {
    int slab = blockIdx.x, b = blockIdx.y, t = threadIdx.x;
    __shared__ float ww_s[128];
    __shared__ float4 rk_s[64];
    __shared__ float4 e_s[16], wv_s[16];
    __shared__ float sk_s[4];

    if (t < 128) ww_s[t] = g_ww[b * M + slab * 128 + t];
    if (t >= 128 && t < 192) rk_s[t - 128] = ((const float4*)(g_keys + b * 256))[t - 128];
    if (t >= 192 && t < 208) e_s[t - 192] = ((const float4*)(g_erase + b * W))[t - 192];
    if (t >= 208 && t < 224) wv_s[t - 208] = ((const float4*)(g_wvec + b * W))[t - 208];
    if (t >= 224 && t < 228) {
        int r = t - 224;
        sk_s[r] = g_kstr[b * 4 + r] / (g_knorm[b * 4 + r] + 1e-6f);
    }
    __syncthreads();

    int row16 = t >> 4, l16 = t & 15;
    const float4* mem4 = (const float4*)(memory + (size_t)b * M * W);
    float4* nm4 = (float4*)(g_newmem + (size_t)b * M * W);
#pragma unroll 2
    for (int pass = 0; pass < 8; pass++) {
        int mi = pass * 16 + row16;
        int m = slab * 128 + mi;
        float wwm = ww_s[mi];
        float4 v = mem4[m * 16 + l16];
        float4 e = e_s[l16], wv = wv_s[l16];
        float4 nm;
        nm.x = fmaf(v.x, fmaf(-wwm, e.x, 1.0f), wwm * wv.x);
        nm.y = fmaf(v.y, fmaf(-wwm, e.y, 1.0f), wwm * wv.y);
        nm.z = fmaf(v.z, fmaf(-wwm, e.z, 1.0f), wwm * wv.z);
        nm.w = fmaf(v.w, fmaf(-wwm, e.w, 1.0f), wwm * wv.w);
        nm4[m * 16 + l16] = nm;
        float ns = nm.x * nm.x + nm.y * nm.y + nm.z * nm.z + nm.w * nm.w;
        float dr0, dr1, dr2, dr3;
        {
            float4 k0 = rk_s[0 * 16 + l16], k1 = rk_s[1 * 16 + l16];
            float4 k2 = rk_s[2 * 16 + l16], k3 = rk_s[3 * 16 + l16];
            dr0 = nm.x * k0.x + nm.y * k0.y + nm.z * k0.z + nm.w * k0.w;
            dr1 = nm.x * k1.x + nm.y * k1.y + nm.z * k1.z + nm.w * k1.w;
            dr2 = nm.x * k2.x + nm.y * k2.y + nm.z * k2.z + nm.w * k2.w;
            dr3 = nm.x * k3.x + nm.y * k3.y + nm.z * k3.z + nm.w * k3.w;
        }
        float g01 = (l16 & 1) ? dr0 : dr1;
        g01 = __shfl_xor_sync(0xffffffffu, g01, 1);
        float a01 = ((l16 & 1) ? dr1 : dr0) + g01;
        float g23 = (l16 & 1) ? dr2 : dr3;
        g23 = __shfl_xor_sync(0xffffffffu, g23, 1);
        float a23 = ((l16 & 1) ? dr3 : dr2) + g23;
        float gx = (l16 & 2) ? a01 : a23;
        gx = __shfl_xor_sync(0xffffffffu, gx, 2);
        float c = ((l16 & 2) ? a23 : a01) + gx;
        c += __shfl_xor_sync(0xffffffffu, c, 4);
        c += __shfl_xor_sync(0xffffffffu, c, 8);
#pragma unroll
        for (int o = 8; o; o >>= 1) ns += __shfl_xor_sync(0xffffffffu, ns, o);
        if (l16 < 4) {
            float inv = 1.0f / (sqrtf(ns) + 1e-6f);
            g_d[(b * 4 + l16) * M + m] = c * sk_s[l16] * inv;
        }
    }
}

// ---------------- K4: link kernel (2 cols/thread) [PROFILED SLOT] ----------------
// G[m,n] = (1-ww[m]-ww[n])*L[m,n] + ww[m]*p[n]  (diag corrected later in k_nrw)
__global__ __launch_bounds__(256, 6) void k_link(const float* __restrict__ link,
                                                 const float* __restrict__ precedence,
                                                 const float* __restrict__ read_weights) {
    int mt = blockIdx.x;   // 0..15 (64-row tiles)
    int nt = blockIdx.y;   // 0..1  (512-col halves)
    int b  = blockIdx.z;
    int t  = threadIdx.x;
    int warp = t >> 5, lane = t & 31;
    __shared__ float ww_row[64];
    __shared__ __align__(16) float4 rw_row[64];
    __shared__ float fw_s[8][4][64];

    if (t < 64) ww_row[t] = g_ww[b * M + mt * 64 + t];
    {
        int r = t >> 6, mi = t & 63;
        ((float*)rw_row)[mi * 4 + r] = read_weights[(b * 4 + r) * M + mt * 64 + mi];
    }

    int n0 = nt * 512 + t * 2;
    float2 wwn = *(const float2*)&g_ww[b * M + n0];
    float2 pn  = *(const float2*)&precedence[b * M + n0];
    float2 rwn0 = *(const float2*)&read_weights[(b * 4 + 0) * M + n0];
    float2 rwn1 = *(const float2*)&read_weights[(b * 4 + 1) * M + n0];
    float2 rwn2 = *(const float2*)&read_weights[(b * 4 + 2) * M + n0];
    float2 rwn3 = *(const float2*)&read_weights[(b * 4 + 3) * M + n0];
    float ax = 1.0f - wwn.x, ay = 1.0f - wwn.y;
    float2 bw0 = {0,0}, bw1 = {0,0}, bw2 = {0,0}, bw3 = {0,0};

    const float2* Lp = (const float2*)(link + (size_t)b * M * M + (size_t)(mt * 64) * M) + (n0 >> 1);
    __syncthreads();

#pragma unroll 4
    for (int mi = 0; mi < 64; mi++) {
        float wwm = ww_row[mi];
        float4 rr4 = rw_row[mi];
        float2 L = *Lp; Lp += (M / 2);
        float nl0 = fmaf(L.x, ax - wwm, wwm * pn.x);
        float nl1 = fmaf(L.y, ay - wwm, wwm * pn.y);

        float f0 = fmaf(nl1, rwn0.y, nl0 * rwn0.x);
        float f1 = fmaf(nl1, rwn1.y, nl0 * rwn1.x);
        float f2 = fmaf(nl1, rwn2.y, nl0 * rwn2.x);
        float f3 = fmaf(nl1, rwn3.y, nl0 * rwn3.x);

        bw0.x = fmaf(nl0, rr4.x, bw0.x); bw0.y = fmaf(nl1, rr4.x, bw0.y);
        bw1.x = fmaf(nl0, rr4.y, bw1.x); bw1.y = fmaf(nl1, rr4.y, bw1.y);
        bw2.x = fmaf(nl0, rr4.z, bw2.x); bw2.y = fmaf(nl1, rr4.z, bw2.y);
        bw3.x = fmaf(nl0, rr4.w, bw3.x); bw3.y = fmaf(nl1, rr4.w, bw3.y);

        float g01 = (lane & 1) ? f0 : f1;
        g01 = __shfl_xor_sync(0xffffffffu, g01, 1);
        float a01 = ((lane & 1) ? f1 : f0) + g01;
        float g23 = (lane & 1) ? f2 : f3;
        g23 = __shfl_xor_sync(0xffffffffu, g23, 1);
        float a23 = ((lane & 1) ? f3 : f2) + g23;
        float gx = (lane & 2) ? a01 : a23;
        gx = __shfl_xor_sync(0xffffffffu, gx, 2);
        float c = ((lane & 2) ? a23 : a01) + gx;
        c += __shfl_xor_sync(0xffffffffu, c, 4);
        c += __shfl_xor_sync(0xffffffffu, c, 8);
        c += __shfl_xor_sync(0xffffffffu, c, 16);
        if (lane < 4) fw_s[warp][lane][mi] = c;
    }
    __syncthreads();
    {
        int rr = t >> 6, mi = t & 63;
        float s = 0.0f;
#pragma unroll
        for (int w = 0; w < 8; w++) s += fw_s[w][rr][mi];
        g_fwp[((b * 2 + nt) * 4 + rr) * M + mt * 64 + mi] = s;
    }
    *(float2*)&g_bwp[((b * 16 + mt) * 4 + 0) * M + n0] = bw0;
    *(float2*)&g_bwp[((b * 16 + mt) * 4 + 1) * M + n0] = bw1;
    *(float2*)&g_bwp[((b * 16 + mt) * 4 + 2) * M + n0] = bw2;
    *(float2*)&g_bwp[((b * 16 + mt) * 4 + 3) * M + n0] = bw3;
}

// ---------------- K5: read-content softmax ----------------
__global__ __launch_bounds__(1024) void k_cwsm() {
    int b = blockIdx.x, t = threadIdx.x;
    __shared__ float red[32];
#pragma unroll
    for (int rr = 0; rr < 4; rr++) {
        float x = g_d[(b * 4 + rr) * M + t];
        float mx = blockMax_(x, red);
        float e = expf(x - mx);
        float sm = blockSum_(e, red);
        g_cw[(b * 4 + rr) * M + t] = e / sm;
    }
}

// ---------------- K6: reduce partials + diag correction + mode combine ----------------
__global__ __launch_bounds__(512) void k_nrw(const float* __restrict__ link,
                                             const float* __restrict__ precedence,
                                             const float* __restrict__ read_weights) {
    int bx = blockIdx.x, b = blockIdx.y, t = threadIdx.x;
    int rr = t >> 7, mi = t & 127;
    int m = bx * 128 + mi;

    float fw = g_fwp[((b * 2 + 0) * 4 + rr) * M + m] + g_fwp[((b * 2 + 1) * 4 + rr) * M + m];
    float bw = 0.0f;
#pragma unroll
    for (int mt = 0; mt < 16; mt++)
        bw += g_bwp[((b * 16 + mt) * 4 + rr) * M + m];

    float wwm = g_ww[b * M + m];
    float pm  = precedence[b * M + m];
    float rwv = read_weights[(b * 4 + rr) * M + m];
    float Ld  = link[(size_t)b * M * M + (size_t)m * (M + 1)];
    float nld = fmaf(1.0f - 2.0f * wwm, Ld, wwm * pm);
    float corr = nld * rwv;
    fw -= corr;
    bw -= corr;

    float rm0 = g_rm[b * 12 + rr * 3 + 0];
    float rm1 = g_rm[b * 12 + rr * 3 + 1];
    float rm2 = g_rm[b * 12 + rr * 3 + 2];
    g_nrw[(b * 4 + rr) * M + m] = rm0 * bw + rm1 * fw + rm2 * g_cw[(b * 4 + rr) * M + m];
}

// ---------------- K7: read vectors GEMV (4-way m-split, 1024 thr) ----------------
__global__ __launch_bounds__(1024) void k_gemv(float* __restrict__ out) {
    int b = blockIdx.x, t = threadIdx.x;
    __shared__ float nrw_s[4 * M];
    __shared__ float part[4][256];
    for (int i = t; i < 4 * M; i += 1024) nrw_s[i] = g_nrw[b * 4 * M + i];
    __syncthreads();
    int q = t >> 8;             // m-quarter 0..3
    int rr = (t >> 6) & 3;      // read head
    int wl = t & 63;            // word index
    const float* nmB = g_newmem + (size_t)b * M * W + (size_t)q * 256 * W;
    const float* nr = nrw_s + rr * M + q * 256;
    float acc = 0.0f;
#pragma unroll 8
    for (int m = 0; m < 256; m++) acc = fmaf(nr[m], nmB[m * W + wl], acc);
    part[q][rr * 64 + wl] = acc;
    __syncthreads();
    if (t < 256) {
        float s = part[0][t] + part[1][t] + part[2][t] + part[3][t];
        out[b * 256 + t] = s;
    }
}

// ---------------- launch ----------------
extern "C" void kernel_launch(void* const* d_in, const int* in_sizes, int n_in,
                              void* d_out, int out_size) {
    const float* xi   = (const float*)d_in[0];
    const float* Wm   = (const float*)d_in[1];
    const float* bW   = (const float*)d_in[2];
    const float* mem  = (const float*)d_in[3];
    const float* link = (const float*)d_in[4];
    const float* prec = (const float*)d_in[5];
    const float* rw   = (const float*)d_in[6];
    const float* wwo  = (const float*)d_in[7];
    const float* uv   = (const float*)d_in[8];
    float* out = (float*)d_out;

    k_ifprep<<<B, 512>>>(xi, Wm, bW, rw, wwo, uv);       // 1
    k_weights<<<B, 1024>>>(mem);                          // 2
    k_memup<<<dim3(8, B), 256>>>(mem);                    // 3
    k_link<<<dim3(16, 2, B), 256>>>(link, prec, rw);      // 4  <- ncu capture slot
    k_cwsm<<<B, 1024>>>();                                // 5
    k_nrw<<<dim3(8, B), 512>>>(link, prec, rw);           // 6
    k_gemv<<<B, 1024>>>(out);                             // 7
}

// round 8
// speedup vs baseline: 2.5132x; 1.2889x over previous
#include <cuda_runtime.h>
#include <cstdint>
#include <math.h>

#define B   64
#define M   1024
#define W   64
#define R   4
#define D   512
#define IF  471

// ---------------- scratch ----------------
__device__ __align__(16) float g_keys[B * R * W];
__device__ float g_kstr[B * R];
__device__ float g_knorm[B * R];
__device__ __align__(16) float g_wkey[B * W];
__device__ float g_wknorm[B];
__device__ float g_ws[B];
__device__ __align__(16) float g_erase[B * W];
__device__ __align__(16) float g_wvec[B * W];
__device__ float g_ag[B], g_wg[B];
__device__ float g_rm[B * R * 3];
__device__ float g_usage[B * M];
__device__ float g_wcd[B * M];
__device__ float g_ww[B * M];
__device__ float g_d[B * R * M];        // e = exp(d - kstr)
__device__ float g_esum[B * R];
__device__ float g_fw[B * R * M];
__device__ __align__(16) float g_bwp[B * 16 * R * M];
__device__ float g_nrw[B * R * M];
__device__ __align__(16) float g_newmem[B * M * W];

// ---------------- helpers ----------------
__device__ __forceinline__ float sigmoidf_(float x) { return 1.0f / (1.0f + expf(-x)); }
__device__ __forceinline__ float softplusf_(float x) { return (x > 20.0f) ? x : log1pf(expf(x)); }

__device__ __forceinline__ float warpMax_(float v) {
#pragma unroll
    for (int o = 16; o; o >>= 1) v = fmaxf(v, __shfl_xor_sync(0xffffffffu, v, o));
    return v;
}
__device__ __forceinline__ float warpSum_(float v) {
#pragma unroll
    for (int o = 16; o; o >>= 1) v += __shfl_xor_sync(0xffffffffu, v, o);
    return v;
}
__device__ __forceinline__ float blockMax_(float v, float* sh) {
    v = warpMax_(v);
    if ((threadIdx.x & 31) == 0) sh[threadIdx.x >> 5] = v;
    __syncthreads();
    float r = sh[threadIdx.x & 31];
    r = warpMax_(r);
    __syncthreads();
    return r;
}
__device__ __forceinline__ float blockSum_(float v, float* sh) {
    v = warpSum_(v);
    if ((threadIdx.x & 31) == 0) sh[threadIdx.x >> 5] = v;
    __syncthreads();
    float r = sh[threadIdx.x & 31];
    r = warpSum_(r);
    __syncthreads();
    return r;
}

// ---------------- K1: iface GEMV + parse + usage (+ zero esum) ----------------
__global__ __launch_bounds__(512) void k_ifprep(const float* __restrict__ xi,
                                                const float* __restrict__ Wm,
                                                const float* __restrict__ bW,
                                                const float* __restrict__ read_weights,
                                                const float* __restrict__ write_weights,
                                                const float* __restrict__ usage_vector) {
    int b = blockIdx.x, t = threadIdx.x;
    __shared__ float xs[D];
    __shared__ float f[IF + 1];
    xs[t] = xi[b * D + t];
    __syncthreads();
    if (t < IF) {
        float acc = bW[t];
#pragma unroll 8
        for (int i = 0; i < D; i++) acc = fmaf(xs[i], Wm[i * IF + t], acc);
        f[t] = acc;
    }
    __syncthreads();

    if (t < 256) g_keys[b * 256 + t] = f[t];
    if (t >= 256 && t < 320) { int i = t - 256; g_wkey[b * W + i] = f[260 + i]; }
    if (t >= 320 && t < 384) { int i = t - 320; g_erase[b * W + i] = sigmoidf_(f[325 + i]); }
    if (t >= 384 && t < 448) { int i = t - 384; g_wvec[b * W + i] = f[389 + i]; }
    if (t < 4) {
        float x = f[256 + t];
        g_kstr[b * 4 + t] = softplusf_(1.0f + fmaxf(x, 0.0f));
        float s = 0.0f;
        for (int i = 0; i < W; i++) { float v = f[t * W + i]; s = fmaf(v, v, s); }
        g_knorm[b * 4 + t] = sqrtf(s);
        g_esum[b * 4 + t] = 0.0f;
    }
    if (t == 4) {
        float x = f[324];
        g_ws[b] = softplusf_(1.0f + fmaxf(x, 0.0f));
        float s = 0.0f;
        for (int i = 0; i < W; i++) { float v = f[260 + i]; s = fmaf(v, v, s); }
        g_wknorm[b] = sqrtf(s);
    }
    if (t == 5) g_ag[b] = sigmoidf_(f[457]);
    if (t == 6) g_wg[b] = sigmoidf_(f[458]);
    if (t >= 8 && t < 11) {
        int j = t - 8;
        float v[4], mx = -1e30f;
        for (int rr = 0; rr < 4; rr++) { v[rr] = f[458 + rr * 3 + j]; mx = fmaxf(mx, v[rr]); }
        float s = 0.0f;
        for (int rr = 0; rr < 4; rr++) { v[rr] = expf(v[rr] - mx); s += v[rr]; }
        for (int rr = 0; rr < 4; rr++) g_rm[b * 12 + rr * 3 + j] = v[rr] / s;
    }

    float fg[4];
#pragma unroll
    for (int rr = 0; rr < 4; rr++) fg[rr] = sigmoidf_(f[453 + rr]);
    for (int m = t; m < M; m += 512) {
        float uv = usage_vector[b * M + m];
        float wwo = write_weights[b * M + m];
        float u = uv + (1.0f - uv) * wwo;
        float psi = 1.0f;
#pragma unroll
        for (int rr = 0; rr < 4; rr++)
            psi *= (1.0f - fg[rr] * read_weights[(b * 4 + rr) * M + m]);
        g_usage[b * M + m] = u * psi;
    }
}

// ---------------- K2: write-content distances (grid 8x64) ----------------
__global__ __launch_bounds__(256) void k_wc(const float* __restrict__ memory) {
    int slab = blockIdx.x, b = blockIdx.y, t = threadIdx.x;
    __shared__ float4 key_s[16];
    __shared__ float sc;
    if (t < 16) key_s[t] = ((const float4*)(g_wkey + b * W))[t];
    if (t == 16) sc = g_ws[b] / (g_wknorm[b] + 1e-6f);
    __syncthreads();
    int row16 = t >> 4, l16 = t & 15;
    const float4* mem4 = (const float4*)(memory + (size_t)b * M * W);
#pragma unroll 2
    for (int pass = 0; pass < 8; pass++) {
        int m = slab * 128 + pass * 16 + row16;
        float4 v = mem4[m * 16 + l16];
        float4 k = key_s[l16];
        float dot = v.x * k.x + v.y * k.y + v.z * k.z + v.w * k.w;
        float ns  = v.x * v.x + v.y * v.y + v.z * v.z + v.w * v.w;
#pragma unroll
        for (int o = 8; o; o >>= 1) {
            dot += __shfl_xor_sync(0xffffffffu, dot, o);
            ns  += __shfl_xor_sync(0xffffffffu, ns, o);
        }
        if (l16 == 0) g_wcd[b * M + m] = dot * sc / (sqrtf(ns) + 1e-6f);
    }
}

// ---------------- K3: softmax(wcd) + allocation sort + ww ----------------
__global__ __launch_bounds__(1024) void k_weights() {
    int b = blockIdx.x, t = threadIdx.x;
    int lane = t & 31, warp = t >> 5;
    __shared__ float dv[M];
    __shared__ float red[32];
    __shared__ unsigned long long ks[M];
    __shared__ float wtot[32];

    {
        float x = g_wcd[b * M + t];
        float mx = blockMax_(x, red);
        float e = expf(x - mx);
        float sm = blockSum_(e, red);
        dv[t] = e / sm;
    }

    float u = 1e-6f + (1.0f - 1e-6f) * g_usage[b * M + t];
    unsigned long long v = ((unsigned long long)__float_as_uint(u) << 32) | (unsigned)t;
#pragma unroll
    for (int k = 2; k <= 32; k <<= 1) {
#pragma unroll
        for (int j = k >> 1; j > 0; j >>= 1) {
            unsigned long long c = __shfl_xor_sync(0xffffffffu, v, j);
            bool keepMin = ((t & j) == 0) == ((t & k) == 0);
            bool less = v < c;
            v = (less == keepMin) ? v : c;
        }
    }
    ks[t] = v;
    __syncthreads();
#pragma unroll
    for (int k = 64; k <= M; k <<= 1) {
        for (int j = k >> 1; j >= 32; j >>= 1) {
            unsigned long long a = ks[t];
            unsigned long long c = ks[t ^ j];
            bool keepMin = ((t & j) == 0) == ((t & k) == 0);
            bool less = a < c;
            v = (less == keepMin) ? a : c;
            __syncthreads();
            ks[t] = v;
            __syncthreads();
        }
#pragma unroll
        for (int j = 16; j > 0; j >>= 1) {
            unsigned long long c = __shfl_xor_sync(0xffffffffu, v, j);
            bool keepMin = ((t & j) == 0) == ((t & k) == 0);
            bool less = v < c;
            v = (less == keepMin) ? v : c;
        }
        if (k < M) { ks[t] = v; __syncthreads(); }
    }
    float su = __uint_as_float((unsigned)(v >> 32));
    float p = su;
#pragma unroll
    for (int o = 1; o < 32; o <<= 1) {
        float q = __shfl_up_sync(0xffffffffu, p, o);
        if (lane >= o) p *= q;
    }
    if (lane == 31) wtot[warp] = p;
    __syncthreads();
    if (warp == 0) {
        float q = wtot[lane];
#pragma unroll
        for (int o = 1; o < 32; o <<= 1) {
            float rr = __shfl_up_sync(0xffffffffu, q, o);
            if (lane >= o) q *= rr;
        }
        wtot[lane] = q;
    }
    __syncthreads();
    if (warp > 0) p *= wtot[warp - 1];

    int idx = (int)(v & 0xffffffffULL);
    float alloc = (1.0f - su) * p;
    float ag = g_ag[b], wg = g_wg[b];
    g_ww[b * M + idx] = wg * (ag * alloc + (1.0f - ag) * dv[idx]);
}

// ---------------- K4: link kernel v4 (4 cols/thread, 64-row tiles) [PROFILED] ----------------
// G[m,n] = (1-ww[m]-ww[n])*L[m,n] + ww[m]*p[n]  (diag corrected in k_nrw)
__global__ __launch_bounds__(256) void k_link(const float* __restrict__ link,
                                              const float* __restrict__ precedence,
                                              const float* __restrict__ read_weights) {
    int mt = blockIdx.x;   // 0..15 (64-row tiles)
    int b  = blockIdx.y;
    int t  = threadIdx.x;
    int warp = t >> 5, lane = t & 31;
    __shared__ float ww_row[64];
    __shared__ __align__(16) float4 rw_row[64];
    __shared__ float fw_s[8][4][64];

    if (t < 64) ww_row[t] = g_ww[b * M + mt * 64 + t];
    {
        int r = t >> 6, mi = t & 63;
        ((float*)rw_row)[mi * 4 + r] = read_weights[(b * 4 + r) * M + mt * 64 + mi];
    }

    int n0 = t * 4;
    float4 wwn = *(const float4*)&g_ww[b * M + n0];
    float4 pn  = *(const float4*)&precedence[b * M + n0];
    float4 a4  = make_float4(1.0f - wwn.x, 1.0f - wwn.y, 1.0f - wwn.z, 1.0f - wwn.w);
    float4 rwn[4];
#pragma unroll
    for (int rr = 0; rr < 4; rr++) rwn[rr] = *(const float4*)&read_weights[(b * 4 + rr) * M + n0];
    float4 bwa[4];
#pragma unroll
    for (int rr = 0; rr < 4; rr++) bwa[rr] = make_float4(0.f, 0.f, 0.f, 0.f);

    const float4* Lp = (const float4*)(link + (size_t)b * M * M + (size_t)(mt * 64) * M) + t;
    __syncthreads();

    float4 L = *Lp;
#pragma unroll 2
    for (int mi = 0; mi < 64; mi++) {
        float4 Ln;
        if (mi < 63) Ln = Lp[256 * (mi + 1)];   // prefetch next row
        float wwm = ww_row[mi];
        float4 rr4 = rw_row[mi];
        float nl0 = fmaf(L.x, a4.x - wwm, wwm * pn.x);
        float nl1 = fmaf(L.y, a4.y - wwm, wwm * pn.y);
        float nl2 = fmaf(L.z, a4.z - wwm, wwm * pn.z);
        float nl3 = fmaf(L.w, a4.w - wwm, wwm * pn.w);

        float f0 = nl0 * rwn[0].x + nl1 * rwn[0].y + nl2 * rwn[0].z + nl3 * rwn[0].w;
        float f1 = nl0 * rwn[1].x + nl1 * rwn[1].y + nl2 * rwn[1].z + nl3 * rwn[1].w;
        float f2 = nl0 * rwn[2].x + nl1 * rwn[2].y + nl2 * rwn[2].z + nl3 * rwn[2].w;
        float f3 = nl0 * rwn[3].x + nl1 * rwn[3].y + nl2 * rwn[3].z + nl3 * rwn[3].w;

        bwa[0].x = fmaf(nl0, rr4.x, bwa[0].x); bwa[0].y = fmaf(nl1, rr4.x, bwa[0].y);
        bwa[0].z = fmaf(nl2, rr4.x, bwa[0].z); bwa[0].w = fmaf(nl3, rr4.x, bwa[0].w);
        bwa[1].x = fmaf(nl0, rr4.y, bwa[1].x); bwa[1].y = fmaf(nl1, rr4.y, bwa[1].y);
        bwa[1].z = fmaf(nl2, rr4.y, bwa[1].z); bwa[1].w = fmaf(nl3, rr4.y, bwa[1].w);
        bwa[2].x = fmaf(nl0, rr4.z, bwa[2].x); bwa[2].y = fmaf(nl1, rr4.z, bwa[2].y);
        bwa[2].z = fmaf(nl2, rr4.z, bwa[2].z); bwa[2].w = fmaf(nl3, rr4.z, bwa[2].w);
        bwa[3].x = fmaf(nl0, rr4.w, bwa[3].x); bwa[3].y = fmaf(nl1, rr4.w, bwa[3].y);
        bwa[3].z = fmaf(nl2, rr4.w, bwa[3].z); bwa[3].w = fmaf(nl3, rr4.w, bwa[3].w);

        // packed 6-SHFL reduction: lane L ends with f_{L&3} summed over warp
        float g01 = (lane & 1) ? f0 : f1;
        g01 = __shfl_xor_sync(0xffffffffu, g01, 1);
        float a01 = ((lane & 1) ? f1 : f0) + g01;
        float g23 = (lane & 1) ? f2 : f3;
        g23 = __shfl_xor_sync(0xffffffffu, g23, 1);
        float a23 = ((lane & 1) ? f3 : f2) + g23;
        float gx = (lane & 2) ? a01 : a23;
        gx = __shfl_xor_sync(0xffffffffu, gx, 2);
        float c = ((lane & 2) ? a23 : a01) + gx;
        c += __shfl_xor_sync(0xffffffffu, c, 4);
        c += __shfl_xor_sync(0xffffffffu, c, 8);
        c += __shfl_xor_sync(0xffffffffu, c, 16);
        if (lane < 4) fw_s[warp][lane][mi] = c;
        L = Ln;
    }
    __syncthreads();
    {
        int rr = t >> 6, mi = t & 63;
        float s = 0.0f;
#pragma unroll
        for (int w = 0; w < 8; w++) s += fw_s[w][rr][mi];
        g_fw[(b * 4 + rr) * M + mt * 64 + mi] = s;   // complete (block covers all cols)
    }
#pragma unroll
    for (int rr = 0; rr < 4; rr++)
        *(float4*)&g_bwp[((b * 16 + mt) * 4 + rr) * M + n0] = bwa[rr];
}

// ---------------- K5: memory update + e = exp(d - kstr) + esum ----------------
__global__ __launch_bounds__(256) void k_memup(const float* __restrict__ memory) {
    int slab = blockIdx.x, b = blockIdx.y, t = threadIdx.x;
    __shared__ float ww_s[128];
    __shared__ float4 rk_s[64];
    __shared__ float4 e_s[16], wv_s[16];
    __shared__ float sk_s[4], kst_s[4];
    __shared__ float spart[64];

    if (t < 128) ww_s[t] = g_ww[b * M + slab * 128 + t];
    if (t >= 128 && t < 192) rk_s[t - 128] = ((const float4*)(g_keys + b * 256))[t - 128];
    if (t >= 192 && t < 208) e_s[t - 192] = ((const float4*)(g_erase + b * W))[t - 192];
    if (t >= 208 && t < 224) wv_s[t - 208] = ((const float4*)(g_wvec + b * W))[t - 208];
    if (t >= 224 && t < 228) {
        int r = t - 224;
        float kst = g_kstr[b * 4 + r];
        sk_s[r] = kst / (g_knorm[b * 4 + r] + 1e-6f);
        kst_s[r] = kst;
    }
    __syncthreads();

    int row16 = t >> 4, l16 = t & 15;
    const float4* mem4 = (const float4*)(memory + (size_t)b * M * W);
    float4* nm4 = (float4*)(g_newmem + (size_t)b * M * W);
    float eacc = 0.0f;
#pragma unroll 2
    for (int pass = 0; pass < 8; pass++) {
        int mi = pass * 16 + row16;
        int m = slab * 128 + mi;
        float wwm = ww_s[mi];
        float4 v = mem4[m * 16 + l16];
        float4 e = e_s[l16], wv = wv_s[l16];
        float4 nm;
        nm.x = fmaf(v.x, fmaf(-wwm, e.x, 1.0f), wwm * wv.x);
        nm.y = fmaf(v.y, fmaf(-wwm, e.y, 1.0f), wwm * wv.y);
        nm.z = fmaf(v.z, fmaf(-wwm, e.z, 1.0f), wwm * wv.z);
        nm.w = fmaf(v.w, fmaf(-wwm, e.w, 1.0f), wwm * wv.w);
        nm4[m * 16 + l16] = nm;
        float ns = nm.x * nm.x + nm.y * nm.y + nm.z * nm.z + nm.w * nm.w;
        float dr0, dr1, dr2, dr3;
        {
            float4 k0 = rk_s[0 * 16 + l16], k1 = rk_s[1 * 16 + l16];
            float4 k2 = rk_s[2 * 16 + l16], k3 = rk_s[3 * 16 + l16];
            dr0 = nm.x * k0.x + nm.y * k0.y + nm.z * k0.z + nm.w * k0.w;
            dr1 = nm.x * k1.x + nm.y * k1.y + nm.z * k1.z + nm.w * k1.w;
            dr2 = nm.x * k2.x + nm.y * k2.y + nm.z * k2.z + nm.w * k2.w;
            dr3 = nm.x * k3.x + nm.y * k3.y + nm.z * k3.z + nm.w * k3.w;
        }
        float g01 = (l16 & 1) ? dr0 : dr1;
        g01 = __shfl_xor_sync(0xffffffffu, g01, 1);
        float a01 = ((l16 & 1) ? dr1 : dr0) + g01;
        float g23 = (l16 & 1) ? dr2 : dr3;
        g23 = __shfl_xor_sync(0xffffffffu, g23, 1);
        float a23 = ((l16 & 1) ? dr3 : dr2) + g23;
        float gx = (l16 & 2) ? a01 : a23;
        gx = __shfl_xor_sync(0xffffffffu, gx, 2);
        float c = ((l16 & 2) ? a23 : a01) + gx;
        c += __shfl_xor_sync(0xffffffffu, c, 4);
        c += __shfl_xor_sync(0xffffffffu, c, 8);
#pragma unroll
        for (int o = 8; o; o >>= 1) ns += __shfl_xor_sync(0xffffffffu, ns, o);
        if (l16 < 4) {
            float inv = 1.0f / (sqrtf(ns) + 1e-6f);
            float d = c * sk_s[l16] * inv;
            float ev = expf(d - kst_s[l16]);   // shift-invariant softmax; d <= kstr
            g_d[(b * 4 + l16) * M + m] = ev;
            eacc += ev;
        }
    }
    if (l16 < 4) spart[l16 * 16 + row16] = eacc;
    __syncthreads();
    if (t < 4) {
        float s = 0.0f;
#pragma unroll
        for (int i = 0; i < 16; i++) s += spart[t * 16 + i];
        atomicAdd(&g_esum[b * 4 + t], s);
    }
}

// ---------------- K6: reduce bw partials + diag corr + cw normalize + mode combine ----------------
__global__ __launch_bounds__(512) void k_nrw(const float* __restrict__ link,
                                             const float* __restrict__ precedence,
                                             const float* __restrict__ read_weights) {
    int bx = blockIdx.x, b = blockIdx.y, t = threadIdx.x;
    int rr = t >> 7, mi = t & 127;
    int m = bx * 128 + mi;

    float fw = g_fw[(b * 4 + rr) * M + m];
    float bw = 0.0f;
#pragma unroll
    for (int mt = 0; mt < 16; mt++)
        bw += g_bwp[((b * 16 + mt) * 4 + rr) * M + m];

    float wwm = g_ww[b * M + m];
    float pm  = precedence[b * M + m];
    float rwv = read_weights[(b * 4 + rr) * M + m];
    float Ld  = link[(size_t)b * M * M + (size_t)m * (M + 1)];
    float nld = fmaf(1.0f - 2.0f * wwm, Ld, wwm * pm);
    float corr = nld * rwv;
    fw -= corr;
    bw -= corr;

    float cw = g_d[(b * 4 + rr) * M + m] / g_esum[b * 4 + rr];
    float rm0 = g_rm[b * 12 + rr * 3 + 0];
    float rm1 = g_rm[b * 12 + rr * 3 + 1];
    float rm2 = g_rm[b * 12 + rr * 3 + 2];
    g_nrw[(b * 4 + rr) * M + m] = rm0 * bw + rm1 * fw + rm2 * cw;
}

// ---------------- K7: read vectors GEMV (4-way m-split, 1024 thr) ----------------
__global__ __launch_bounds__(1024) void k_gemv(float* __restrict__ out) {
    int b = blockIdx.x, t = threadIdx.x;
    __shared__ float nrw_s[4 * M];
    __shared__ float part[4][256];
    for (int i = t; i < 4 * M; i += 1024) nrw_s[i] = g_nrw[b * 4 * M + i];
    __syncthreads();
    int q = t >> 8;
    int rr = (t >> 6) & 3;
    int wl = t & 63;
    const float* nmB = g_newmem + (size_t)b * M * W + (size_t)q * 256 * W;
    const float* nr = nrw_s + rr * M + q * 256;
    float acc = 0.0f;
#pragma unroll 8
    for (int m = 0; m < 256; m++) acc = fmaf(nr[m], nmB[m * W + wl], acc);
    part[q][rr * 64 + wl] = acc;
    __syncthreads();
    if (t < 256) {
        float s = part[0][t] + part[1][t] + part[2][t] + part[3][t];
        out[b * 256 + t] = s;
    }
}

// ---------------- launch ----------------
extern "C" void kernel_launch(void* const* d_in, const int* in_sizes, int n_in,
                              void* d_out, int out_size) {
    const float* xi   = (const float*)d_in[0];
    const float* Wm   = (const float*)d_in[1];
    const float* bW   = (const float*)d_in[2];
    const float* mem  = (const float*)d_in[3];
    const float* link = (const float*)d_in[4];
    const float* prec = (const float*)d_in[5];
    const float* rw   = (const float*)d_in[6];
    const float* wwo  = (const float*)d_in[7];
    const float* uv   = (const float*)d_in[8];
    float* out = (float*)d_out;

    k_ifprep<<<B, 512>>>(xi, Wm, bW, rw, wwo, uv);       // 1
    k_wc<<<dim3(8, B), 256>>>(mem);                       // 2
    k_weights<<<B, 1024>>>();                             // 3
    k_link<<<dim3(16, B), 256>>>(link, prec, rw);         // 4  <- ncu capture slot
    k_memup<<<dim3(8, B), 256>>>(mem);                    // 5
    k_nrw<<<dim3(8, B), 512>>>(link, prec, rw);           // 6
    k_gemv<<<B, 1024>>>(out);                             // 7
}

// round 9
// speedup vs baseline: 2.6499x; 1.0544x over previous
#include <cuda_runtime.h>
#include <cstdint>
#include <math.h>

#define B   64
#define M   1024
#define W   64
#define R   4
#define D   512
#define IF  471

// ---------------- scratch ----------------
__device__ __align__(16) float g_keys[B * R * W];
__device__ float g_kstr[B * R];
__device__ float g_knorm[B * R];
__device__ __align__(16) float g_wkey[B * W];
__device__ float g_wknorm[B];
__device__ float g_ws[B];
__device__ __align__(16) float g_erase[B * W];
__device__ __align__(16) float g_wvec[B * W];
__device__ float g_ag[B], g_wg[B];
__device__ float g_rm[B * R * 3];
__device__ float g_usage[B * M];
__device__ float g_wcd[B * M];
__device__ float g_ww[B * M];
__device__ float g_d[B * R * M];        // e = exp(d - kstr)
__device__ float g_esum[B * R];
__device__ __align__(16) float g_fw[B * R * M];
__device__ __align__(16) float g_bwp[B * 16 * R * M];
__device__ __align__(16) float g_newmem[B * M * W];

// ---------------- helpers ----------------
__device__ __forceinline__ float sigmoidf_(float x) { return 1.0f / (1.0f + expf(-x)); }
__device__ __forceinline__ float softplusf_(float x) { return (x > 20.0f) ? x : log1pf(expf(x)); }

__device__ __forceinline__ unsigned long long pack2_(float lo, float hi) {
    unsigned long long r;
    asm("mov.b64 %0, {%1, %2};" : "=l"(r) : "f"(lo), "f"(hi));
    return r;
}
__device__ __forceinline__ void unpack2_(unsigned long long v, float& lo, float& hi) {
    asm("mov.b64 {%0, %1}, %2;" : "=f"(lo), "=f"(hi) : "l"(v));
}
__device__ __forceinline__ unsigned long long fma2_(unsigned long long a, unsigned long long b, unsigned long long c) {
    unsigned long long d;
    asm("fma.rn.f32x2 %0, %1, %2, %3;" : "=l"(d) : "l"(a), "l"(b), "l"(c));
    return d;
}
__device__ __forceinline__ unsigned long long mul2_(unsigned long long a, unsigned long long b) {
    unsigned long long d;
    asm("mul.rn.f32x2 %0, %1, %2;" : "=l"(d) : "l"(a), "l"(b));
    return d;
}
__device__ __forceinline__ unsigned long long add2_(unsigned long long a, unsigned long long b) {
    unsigned long long d;
    asm("add.rn.f32x2 %0, %1, %2;" : "=l"(d) : "l"(a), "l"(b));
    return d;
}

__device__ __forceinline__ float warpMax_(float v) {
#pragma unroll
    for (int o = 16; o; o >>= 1) v = fmaxf(v, __shfl_xor_sync(0xffffffffu, v, o));
    return v;
}
__device__ __forceinline__ float warpSum_(float v) {
#pragma unroll
    for (int o = 16; o; o >>= 1) v += __shfl_xor_sync(0xffffffffu, v, o);
    return v;
}
__device__ __forceinline__ float blockMax_(float v, float* sh) {
    v = warpMax_(v);
    if ((threadIdx.x & 31) == 0) sh[threadIdx.x >> 5] = v;
    __syncthreads();
    float r = sh[threadIdx.x & 31];
    r = warpMax_(r);
    __syncthreads();
    return r;
}
__device__ __forceinline__ float blockSum_(float v, float* sh) {
    v = warpSum_(v);
    if ((threadIdx.x & 31) == 0) sh[threadIdx.x >> 5] = v;
    __syncthreads();
    float r = sh[threadIdx.x & 31];
    r = warpSum_(r);
    __syncthreads();
    return r;
}

// ---------------- K1: iface GEMV (2-way D-split) + parse + usage ----------------
__global__ __launch_bounds__(1024) void k_ifprep(const float* __restrict__ xi,
                                                 const float* __restrict__ Wm,
                                                 const float* __restrict__ bW,
                                                 const float* __restrict__ read_weights,
                                                 const float* __restrict__ write_weights,
                                                 const float* __restrict__ usage_vector) {
    int b = blockIdx.x, t = threadIdx.x;
    __shared__ float xs[D];
    __shared__ float f[IF + 1];
    __shared__ float fpart[512];
    if (t < D) xs[t] = xi[b * D + t];
    __syncthreads();
    {
        int j = t & 511, half = t >> 9;
        if (j < IF) {
            const float* Wp = Wm + (size_t)(half * 256) * IF + j;
            const float* xh = xs + half * 256;
            float acc = 0.0f;
#pragma unroll 8
            for (int i = 0; i < 256; i++) acc = fmaf(xh[i], Wp[(size_t)i * IF], acc);
            if (half) fpart[j] = acc;
            else      f[j] = acc;   // provisional; combined below
        }
        __syncthreads();
        if (half == 0 && j < IF) f[j] = f[j] + fpart[j] + bW[j];
        __syncthreads();
    }

    if (t < 256) g_keys[b * 256 + t] = f[t];
    if (t >= 256 && t < 320) { int i = t - 256; g_wkey[b * W + i] = f[260 + i]; }
    if (t >= 320 && t < 384) { int i = t - 320; g_erase[b * W + i] = sigmoidf_(f[325 + i]); }
    if (t >= 384 && t < 448) { int i = t - 384; g_wvec[b * W + i] = f[389 + i]; }
    if (t < 4) {
        float x = f[256 + t];
        g_kstr[b * 4 + t] = softplusf_(1.0f + fmaxf(x, 0.0f));
        float s = 0.0f;
        for (int i = 0; i < W; i++) { float v = f[t * W + i]; s = fmaf(v, v, s); }
        g_knorm[b * 4 + t] = sqrtf(s);
        g_esum[b * 4 + t] = 0.0f;
    }
    if (t == 4) {
        float x = f[324];
        g_ws[b] = softplusf_(1.0f + fmaxf(x, 0.0f));
        float s = 0.0f;
        for (int i = 0; i < W; i++) { float v = f[260 + i]; s = fmaf(v, v, s); }
        g_wknorm[b] = sqrtf(s);
    }
    if (t == 5) g_ag[b] = sigmoidf_(f[457]);
    if (t == 6) g_wg[b] = sigmoidf_(f[458]);
    if (t >= 8 && t < 11) {
        int j = t - 8;
        float v[4], mx = -1e30f;
        for (int rr = 0; rr < 4; rr++) { v[rr] = f[458 + rr * 3 + j]; mx = fmaxf(mx, v[rr]); }
        float s = 0.0f;
        for (int rr = 0; rr < 4; rr++) { v[rr] = expf(v[rr] - mx); s += v[rr]; }
        for (int rr = 0; rr < 4; rr++) g_rm[b * 12 + rr * 3 + j] = v[rr] / s;
    }

    float fg0 = sigmoidf_(f[453]), fg1 = sigmoidf_(f[454]);
    float fg2 = sigmoidf_(f[455]), fg3 = sigmoidf_(f[456]);
    for (int m = t; m < M; m += 1024) {
        float uv = usage_vector[b * M + m];
        float wwo = write_weights[b * M + m];
        float u = uv + (1.0f - uv) * wwo;
        float psi = (1.0f - fg0 * read_weights[(b * 4 + 0) * M + m])
                  * (1.0f - fg1 * read_weights[(b * 4 + 1) * M + m])
                  * (1.0f - fg2 * read_weights[(b * 4 + 2) * M + m])
                  * (1.0f - fg3 * read_weights[(b * 4 + 3) * M + m]);
        g_usage[b * M + m] = u * psi;
    }
}

// ---------------- K2: write-content distances (grid 8x64) ----------------
__global__ __launch_bounds__(256) void k_wc(const float* __restrict__ memory) {
    int slab = blockIdx.x, b = blockIdx.y, t = threadIdx.x;
    __shared__ float4 key_s[16];
    __shared__ float sc;
    if (t < 16) key_s[t] = ((const float4*)(g_wkey + b * W))[t];
    if (t == 16) sc = g_ws[b] / (g_wknorm[b] + 1e-6f);
    __syncthreads();
    int row16 = t >> 4, l16 = t & 15;
    const float4* mem4 = (const float4*)(memory + (size_t)b * M * W);
#pragma unroll 2
    for (int pass = 0; pass < 8; pass++) {
        int m = slab * 128 + pass * 16 + row16;
        float4 v = mem4[m * 16 + l16];
        float4 k = key_s[l16];
        float dot = v.x * k.x + v.y * k.y + v.z * k.z + v.w * k.w;
        float ns  = v.x * v.x + v.y * v.y + v.z * v.z + v.w * v.w;
#pragma unroll
        for (int o = 8; o; o >>= 1) {
            dot += __shfl_xor_sync(0xffffffffu, dot, o);
            ns  += __shfl_xor_sync(0xffffffffu, ns, o);
        }
        if (l16 == 0) g_wcd[b * M + m] = dot * sc / (sqrtf(ns) + 1e-6f);
    }
}

// ---------------- K3: softmax(wcd) + allocation sort + ww ----------------
__global__ __launch_bounds__(1024) void k_weights() {
    int b = blockIdx.x, t = threadIdx.x;
    int lane = t & 31, warp = t >> 5;
    __shared__ float dv[M];
    __shared__ float red[32];
    __shared__ unsigned long long ks[M];
    __shared__ float wtot[32];

    {
        float x = g_wcd[b * M + t];
        float mx = blockMax_(x, red);
        float e = expf(x - mx);
        float sm = blockSum_(e, red);
        dv[t] = e / sm;
    }

    float u = 1e-6f + (1.0f - 1e-6f) * g_usage[b * M + t];
    unsigned long long v = ((unsigned long long)__float_as_uint(u) << 32) | (unsigned)t;
#pragma unroll
    for (int k = 2; k <= 32; k <<= 1) {
#pragma unroll
        for (int j = k >> 1; j > 0; j >>= 1) {
            unsigned long long c = __shfl_xor_sync(0xffffffffu, v, j);
            bool keepMin = ((t & j) == 0) == ((t & k) == 0);
            bool less = v < c;
            v = (less == keepMin) ? v : c;
        }
    }
    ks[t] = v;
    __syncthreads();
#pragma unroll
    for (int k = 64; k <= M; k <<= 1) {
        for (int j = k >> 1; j >= 32; j >>= 1) {
            unsigned long long a = ks[t];
            unsigned long long c = ks[t ^ j];
            bool keepMin = ((t & j) == 0) == ((t & k) == 0);
            bool less = a < c;
            v = (less == keepMin) ? a : c;
            __syncthreads();
            ks[t] = v;
            __syncthreads();
        }
#pragma unroll
        for (int j = 16; j > 0; j >>= 1) {
            unsigned long long c = __shfl_xor_sync(0xffffffffu, v, j);
            bool keepMin = ((t & j) == 0) == ((t & k) == 0);
            bool less = v < c;
            v = (less == keepMin) ? v : c;
        }
        if (k < M) { ks[t] = v; __syncthreads(); }
    }
    float su = __uint_as_float((unsigned)(v >> 32));
    float p = su;
#pragma unroll
    for (int o = 1; o < 32; o <<= 1) {
        float q = __shfl_up_sync(0xffffffffu, p, o);
        if (lane >= o) p *= q;
    }
    if (lane == 31) wtot[warp] = p;
    __syncthreads();
    if (warp == 0) {
        float q = wtot[lane];
#pragma unroll
        for (int o = 1; o < 32; o <<= 1) {
            float rr = __shfl_up_sync(0xffffffffu, q, o);
            if (lane >= o) q *= rr;
        }
        wtot[lane] = q;
    }
    __syncthreads();
    if (warp > 0) p *= wtot[warp - 1];

    int idx = (int)(v & 0xffffffffULL);
    float alloc = (1.0f - su) * p;
    float ag = g_ag[b], wg = g_wg[b];
    g_ww[b * M + idx] = wg * (ag * alloc + (1.0f - ag) * dv[idx]);
}

// ---------------- K4: link kernel v5 (f32x2 packed) [PROFILED] ----------------
// G[m,n] = (1-ww[m]-ww[n])*L[m,n] + ww[m]*p[n]  (diag corrected in k_gemv)
__global__ __launch_bounds__(256) void k_link(const float* __restrict__ link,
                                              const float* __restrict__ precedence,
                                              const float* __restrict__ read_weights) {
    int mt = blockIdx.x;   // 0..15 (64-row tiles)
    int b  = blockIdx.y;
    int t  = threadIdx.x;
    int warp = t >> 5, lane = t & 31;
    __shared__ float ww_row[64];
    __shared__ __align__(16) float4 rw_row[64];
    __shared__ float fw_s[8][4][64];

    if (t < 64) ww_row[t] = g_ww[b * M + mt * 64 + t];
    {
        int r = t >> 6, mi = t & 63;
        ((float*)rw_row)[mi * 4 + r] = read_weights[(b * 4 + r) * M + mt * 64 + mi];
    }

    int n0 = t * 4;
    float4 wwn = *(const float4*)&g_ww[b * M + n0];
    float4 pnf = *(const float4*)&precedence[b * M + n0];
    unsigned long long a01 = pack2_(1.0f - wwn.x, 1.0f - wwn.y);
    unsigned long long a23 = pack2_(1.0f - wwn.z, 1.0f - wwn.w);
    unsigned long long pn01 = pack2_(pnf.x, pnf.y);
    unsigned long long pn23 = pack2_(pnf.z, pnf.w);
    unsigned long long rwn01[4], rwn23[4];
#pragma unroll
    for (int rr = 0; rr < 4; rr++) {
        float4 rv = *(const float4*)&read_weights[(b * 4 + rr) * M + n0];
        rwn01[rr] = pack2_(rv.x, rv.y);
        rwn23[rr] = pack2_(rv.z, rv.w);
    }
    unsigned long long bwa01[4] = {0ull, 0ull, 0ull, 0ull};
    unsigned long long bwa23[4] = {0ull, 0ull, 0ull, 0ull};

    const ulonglong2* Lp = (const ulonglong2*)(link + (size_t)b * M * M + (size_t)(mt * 64) * M) + t;
    __syncthreads();

    ulonglong2 L = *Lp;
#pragma unroll 2
    for (int mi = 0; mi < 64; mi++) {
        ulonglong2 Ln;
        if (mi < 63) Ln = Lp[256 * (mi + 1)];   // prefetch next row
        float wwm = ww_row[mi];
        float4 rr4 = rw_row[mi];
        unsigned long long wwm2 = pack2_(wwm, wwm);
        unsigned long long nww2 = pack2_(-wwm, -wwm);
        unsigned long long c01 = add2_(a01, nww2);
        unsigned long long c23 = add2_(a23, nww2);
        unsigned long long nl01 = fma2_(L.x, c01, mul2_(wwm2, pn01));
        unsigned long long nl23 = fma2_(L.y, c23, mul2_(wwm2, pn23));

        // fw: packed dot + horizontal
        float f0, f1, f2, f3;
        {
            float lo, hi;
            unsigned long long p0 = fma2_(nl23, rwn23[0], mul2_(nl01, rwn01[0]));
            unpack2_(p0, lo, hi); f0 = lo + hi;
            unsigned long long p1 = fma2_(nl23, rwn23[1], mul2_(nl01, rwn01[1]));
            unpack2_(p1, lo, hi); f1 = lo + hi;
            unsigned long long p2 = fma2_(nl23, rwn23[2], mul2_(nl01, rwn01[2]));
            unpack2_(p2, lo, hi); f2 = lo + hi;
            unsigned long long p3 = fma2_(nl23, rwn23[3], mul2_(nl01, rwn01[3]));
            unpack2_(p3, lo, hi); f3 = lo + hi;
        }

        // bw: packed accumulate with broadcast rw
        {
            unsigned long long r2;
            r2 = pack2_(rr4.x, rr4.x);
            bwa01[0] = fma2_(nl01, r2, bwa01[0]); bwa23[0] = fma2_(nl23, r2, bwa23[0]);
            r2 = pack2_(rr4.y, rr4.y);
            bwa01[1] = fma2_(nl01, r2, bwa01[1]); bwa23[1] = fma2_(nl23, r2, bwa23[1]);
            r2 = pack2_(rr4.z, rr4.z);
            bwa01[2] = fma2_(nl01, r2, bwa01[2]); bwa23[2] = fma2_(nl23, r2, bwa23[2]);
            r2 = pack2_(rr4.w, rr4.w);
            bwa01[3] = fma2_(nl01, r2, bwa01[3]); bwa23[3] = fma2_(nl23, r2, bwa23[3]);
        }

        // packed 6-SHFL reduction: lane L ends with f_{L&3} summed over warp
        float g01 = (lane & 1) ? f0 : f1;
        g01 = __shfl_xor_sync(0xffffffffu, g01, 1);
        float a01s = ((lane & 1) ? f1 : f0) + g01;
        float g23 = (lane & 1) ? f2 : f3;
        g23 = __shfl_xor_sync(0xffffffffu, g23, 1);
        float a23s = ((lane & 1) ? f3 : f2) + g23;
        float gx = (lane & 2) ? a01s : a23s;
        gx = __shfl_xor_sync(0xffffffffu, gx, 2);
        float c = ((lane & 2) ? a23s : a01s) + gx;
        c += __shfl_xor_sync(0xffffffffu, c, 4);
        c += __shfl_xor_sync(0xffffffffu, c, 8);
        c += __shfl_xor_sync(0xffffffffu, c, 16);
        if (lane < 4) fw_s[warp][lane][mi] = c;
        L = Ln;
    }
    __syncthreads();
    {
        int rr = t >> 6, mi = t & 63;
        float s = 0.0f;
#pragma unroll
        for (int w = 0; w < 8; w++) s += fw_s[w][rr][mi];
        g_fw[(b * 4 + rr) * M + mt * 64 + mi] = s;
    }
#pragma unroll
    for (int rr = 0; rr < 4; rr++) {
        ulonglong2 s; s.x = bwa01[rr]; s.y = bwa23[rr];
        *(ulonglong2*)&g_bwp[((b * 16 + mt) * 4 + rr) * M + n0] = s;
    }
}

// ---------------- K5: memory update + e = exp(d - kstr) + esum ----------------
__global__ __launch_bounds__(256) void k_memup(const float* __restrict__ memory) {
    int slab = blockIdx.x, b = blockIdx.y, t = threadIdx.x;
    __shared__ float ww_s[128];
    __shared__ float4 rk_s[64];
    __shared__ float4 e_s[16], wv_s[16];
    __shared__ float sk_s[4], kst_s[4];
    __shared__ float spart[64];

    if (t < 128) ww_s[t] = g_ww[b * M + slab * 128 + t];
    if (t >= 128 && t < 192) rk_s[t - 128] = ((const float4*)(g_keys + b * 256))[t - 128];
    if (t >= 192 && t < 208) e_s[t - 192] = ((const float4*)(g_erase + b * W))[t - 192];
    if (t >= 208 && t < 224) wv_s[t - 208] = ((const float4*)(g_wvec + b * W))[t - 208];
    if (t >= 224 && t < 228) {
        int r = t - 224;
        float kst = g_kstr[b * 4 + r];
        sk_s[r] = kst / (g_knorm[b * 4 + r] + 1e-6f);
        kst_s[r] = kst;
    }
    __syncthreads();

    int row16 = t >> 4, l16 = t & 15;
    const float4* mem4 = (const float4*)(memory + (size_t)b * M * W);
    float4* nm4 = (float4*)(g_newmem + (size_t)b * M * W);
    float eacc = 0.0f;
#pragma unroll 2
    for (int pass = 0; pass < 8; pass++) {
        int mi = pass * 16 + row16;
        int m = slab * 128 + mi;
        float wwm = ww_s[mi];
        float4 v = mem4[m * 16 + l16];
        float4 e = e_s[l16], wv = wv_s[l16];
        float4 nm;
        nm.x = fmaf(v.x, fmaf(-wwm, e.x, 1.0f), wwm * wv.x);
        nm.y = fmaf(v.y, fmaf(-wwm, e.y, 1.0f), wwm * wv.y);
        nm.z = fmaf(v.z, fmaf(-wwm, e.z, 1.0f), wwm * wv.z);
        nm.w = fmaf(v.w, fmaf(-wwm, e.w, 1.0f), wwm * wv.w);
        nm4[m * 16 + l16] = nm;
        float ns = nm.x * nm.x + nm.y * nm.y + nm.z * nm.z + nm.w * nm.w;
        float dr0, dr1, dr2, dr3;
        {
            float4 k0 = rk_s[0 * 16 + l16], k1 = rk_s[1 * 16 + l16];
            float4 k2 = rk_s[2 * 16 + l16], k3 = rk_s[3 * 16 + l16];
            dr0 = nm.x * k0.x + nm.y * k0.y + nm.z * k0.z + nm.w * k0.w;
            dr1 = nm.x * k1.x + nm.y * k1.y + nm.z * k1.z + nm.w * k1.w;
            dr2 = nm.x * k2.x + nm.y * k2.y + nm.z * k2.z + nm.w * k2.w;
            dr3 = nm.x * k3.x + nm.y * k3.y + nm.z * k3.z + nm.w * k3.w;
        }
        float g01 = (l16 & 1) ? dr0 : dr1;
        g01 = __shfl_xor_sync(0xffffffffu, g01, 1);
        float a01 = ((l16 & 1) ? dr1 : dr0) + g01;
        float g23 = (l16 & 1) ? dr2 : dr3;
        g23 = __shfl_xor_sync(0xffffffffu, g23, 1);
        float a23 = ((l16 & 1) ? dr3 : dr2) + g23;
        float gx = (l16 & 2) ? a01 : a23;
        gx = __shfl_xor_sync(0xffffffffu, gx, 2);
        float c = ((l16 & 2) ? a23 : a01) + gx;
        c += __shfl_xor_sync(0xffffffffu, c, 4);
        c += __shfl_xor_sync(0xffffffffu, c, 8);
#pragma unroll
        for (int o = 8; o; o >>= 1) ns += __shfl_xor_sync(0xffffffffu, ns, o);
        if (l16 < 4) {
            float inv = 1.0f / (sqrtf(ns) + 1e-6f);
            float d = c * sk_s[l16] * inv;
            float ev = expf(d - kst_s[l16]);   // shift-invariant softmax; d <= kstr
            g_d[(b * 4 + l16) * M + m] = ev;
            eacc += ev;
        }
    }
    if (l16 < 4) spart[l16 * 16 + row16] = eacc;
    __syncthreads();
    if (t < 4) {
        float s = 0.0f;
#pragma unroll
        for (int i = 0; i < 16; i++) s += spart[t * 16 + i];
        atomicAdd(&g_esum[b * 4 + t], s);
    }
}

// ---------------- K6: nrw (reduce partials + diag corr + modes) + read-vector GEMV ----------------
__global__ __launch_bounds__(1024) void k_gemv(const float* __restrict__ link,
                                               const float* __restrict__ precedence,
                                               const float* __restrict__ read_weights,
                                               float* __restrict__ out) {
    int b = blockIdx.x, t = threadIdx.x;
    __shared__ float nrw_s[4 * M];
    __shared__ float part[4][256];

    // phase 1: nrw
    {
        int rr = t >> 8, m0 = (t & 255) * 4;
        float4 fw4 = *(const float4*)&g_fw[(b * 4 + rr) * M + m0];
        float4 bw4 = make_float4(0.f, 0.f, 0.f, 0.f);
#pragma unroll
        for (int mt = 0; mt < 16; mt++) {
            float4 p = *(const float4*)&g_bwp[((b * 16 + mt) * 4 + rr) * M + m0];
            bw4.x += p.x; bw4.y += p.y; bw4.z += p.z; bw4.w += p.w;
        }
        float4 ww4 = *(const float4*)&g_ww[b * M + m0];
        float4 pm4 = *(const float4*)&precedence[b * M + m0];
        float4 rw4 = *(const float4*)&read_weights[(b * 4 + rr) * M + m0];
        float4 d4  = *(const float4*)&g_d[(b * 4 + rr) * M + m0];
        float es = g_esum[b * 4 + rr];
        float rm0 = g_rm[b * 12 + rr * 3 + 0];
        float rm1 = g_rm[b * 12 + rr * 3 + 1];
        float rm2 = g_rm[b * 12 + rr * 3 + 2];
        const float* Lb = link + (size_t)b * M * M;
        float fwv[4] = {fw4.x, fw4.y, fw4.z, fw4.w};
        float bwv[4] = {bw4.x, bw4.y, bw4.z, bw4.w};
        float wwv[4] = {ww4.x, ww4.y, ww4.z, ww4.w};
        float pmv[4] = {pm4.x, pm4.y, pm4.z, pm4.w};
        float rwv[4] = {rw4.x, rw4.y, rw4.z, rw4.w};
        float dv4[4] = {d4.x, d4.y, d4.z, d4.w};
#pragma unroll
        for (int k = 0; k < 4; k++) {
            int m = m0 + k;
            float Ld = Lb[(size_t)m * (M + 1)];
            float nld = fmaf(1.0f - 2.0f * wwv[k], Ld, wwv[k] * pmv[k]);
            float corr = nld * rwv[k];
            nrw_s[rr * M + m] = rm0 * (bwv[k] - corr) + rm1 * (fwv[k] - corr) + rm2 * (dv4[k] / es);
        }
    }
    __syncthreads();

    // phase 2: out[b,r,w] = sum_m nrw[r][m] * newmem[m][w]  (4-way m-split)
    int q = t >> 8;
    int rr = (t >> 6) & 3;
    int wl = t & 63;
    const float* nmB = g_newmem + (size_t)b * M * W + (size_t)q * 256 * W;
    const float* nr = nrw_s + rr * M + q * 256;
    float acc = 0.0f;
#pragma unroll 8
    for (int m = 0; m < 256; m++) acc = fmaf(nr[m], nmB[m * W + wl], acc);
    part[q][rr * 64 + wl] = acc;
    __syncthreads();
    if (t < 256) {
        float s = part[0][t] + part[1][t] + part[2][t] + part[3][t];
        out[b * 256 + t] = s;
    }
}

// ---------------- launch ----------------
extern "C" void kernel_launch(void* const* d_in, const int* in_sizes, int n_in,
                              void* d_out, int out_size) {
    const float* xi   = (const float*)d_in[0];
    const float* Wm   = (const float*)d_in[1];
    const float* bW   = (const float*)d_in[2];
    const float* mem  = (const float*)d_in[3];
    const float* link = (const float*)d_in[4];
    const float* prec = (const float*)d_in[5];
    const float* rw   = (const float*)d_in[6];
    const float* wwo  = (const float*)d_in[7];
    const float* uv   = (const float*)d_in[8];
    float* out = (float*)d_out;

    k_ifprep<<<B, 1024>>>(xi, Wm, bW, rw, wwo, uv);      // 1
    k_wc<<<dim3(8, B), 256>>>(mem);                       // 2
    k_weights<<<B, 1024>>>();                             // 3
    k_link<<<dim3(16, B), 256>>>(link, prec, rw);         // 4  <- ncu capture slot
    k_memup<<<dim3(8, B), 256>>>(mem);                    // 5
    k_gemv<<<B, 1024>>>(link, prec, rw, out);             // 6
}